// round 14
// baseline (speedup 1.0000x reference)
#include <cuda_runtime.h>
#include <cstdint>

#define NB 4
typedef unsigned long long ull;

// ---------------- static device scratch ----------------
__device__ float g_nx1[NB*2048*3];
__device__ float g_nx2[NB*1024*3];
__device__ float g_nx3[NB*512*3];
__device__ float g_f1[NB*2048*128];
__device__ float g_f2[NB*1024*256];
__device__ float g_f3[NB*512*512];
__device__ int   g_fidx[NB*2048];
__device__ int   g_fidx2[NB*1024];
__device__ int   g_nidx[720896];     // nidx1@0 | nidx2@524288 | nidx3@655360 | nidx4@688128
__device__ float g_YA[33554432];
__device__ float g_YB[16777216];
__device__ float4 g_pk4[NB*16384];
__device__ int   g_fps_prog[NB];
__device__ int   g_bqdone[1024];

__device__ __forceinline__ uint32_t smem_u32(const void* p) {
    uint32_t a;
    asm("{ .reg .u64 t; cvta.to.shared.u64 t, %1; cvt.u32.u64 %0, t; }" : "=r"(a) : "l"(p));
    return a;
}
__device__ __forceinline__ ull pkxy(float x, float y) {
    ull r; asm("mov.b64 %0, {%1, %2};" : "=l"(r) : "f"(x), "f"(y)); return r;
}
__device__ __forceinline__ void upkxy(ull v, float& x, float& y) {
    asm("mov.b64 {%0, %1}, %2;" : "=f"(x), "=f"(y) : "l"(v));
}
__device__ __forceinline__ int ld_acq(const int* p) {
    int v; asm volatile("ld.global.acquire.gpu.b32 %0, [%1];" : "=r"(v) : "l"(p) : "memory"); return v;
}
__device__ __forceinline__ void st_rel(int* p, int v) {
    asm volatile("st.global.release.gpu.b32 [%0], %1;" :: "l"(p), "r"(v) : "memory");
}

// ================== fps1 body: 8-CTA cluster, 256 thr (R12-proven) + progress publish ==================
#define CLU 8
__device__ __forceinline__ void fps1_dev(const float* __restrict__ xyz, int* __restrict__ fidx,
                                         float* __restrict__ nxyz, int bid, int* prog)
{
    __shared__ ull   s_wk[8];
    __shared__ ull   s_wxy[8];
    __shared__ float s_wz[8];
    __shared__ __align__(16) ull s_ex[2][2];
    __shared__ float s_exz[2];

    const int t = threadIdx.x, lane = t & 31, w = t >> 5;
    uint32_t rank; asm("mov.u32 %0, %%cluster_ctarank;" : "=r"(rank));
    const int b = bid / CLU;
    const float* base = xyz + (size_t)b*16384*3;

    float px[8], py[8], pz[8], dd[8];
#pragma unroll
    for (int k = 0; k < 8; k++) {
        int i = (int)rank*2048 + k*256 + t;
        px[k] = base[i*3]; py[k] = base[i*3+1]; pz[k] = base[i*3+2];
        dd[k] = 1e10f;
    }
    float cx = base[0], cy = base[1], cz = base[2];
    if (rank == 0 && t == 0) {
        fidx[(size_t)b*2048] = 0;
        float* o = nxyz + (size_t)b*2048*3;
        o[0] = cx; o[1] = cy; o[2] = cz;
        st_rel(&prog[b], 1);
    }

    for (int j = 1; j < 2048; j++) {
        const int p = j & 1;
        float bd = -1.0f, bx = 0, by = 0, bz = 0; int bidx = 0;
#pragma unroll
        for (int k = 0; k < 8; k++) {
            float dx = px[k]-cx, dy = py[k]-cy, dz = pz[k]-cz;
            float nd = fminf(dd[k], dx*dx + dy*dy + dz*dz);
            dd[k] = nd;
            if (nd > bd) { bd = nd; bidx = (int)rank*2048 + k*256 + t; bx = px[k]; by = py[k]; bz = pz[k]; }
        }
        ull key = ((ull)__float_as_uint(bd) << 32) | (ull)(16383 - bidx);
        ull xy  = pkxy(bx, by);
#pragma unroll
        for (int o = 16; o; o >>= 1) {
            ull  ok = __shfl_xor_sync(0xffffffffu, key, o);
            ull  oxy= __shfl_xor_sync(0xffffffffu, xy,  o);
            float oz= __shfl_xor_sync(0xffffffffu, bz,  o);
            if (ok > key) { key = ok; xy = oxy; bz = oz; }
        }
        if (lane == 0) { s_wk[w] = key; s_wxy[w] = xy; s_wz[w] = bz; }
        __syncthreads();
        if (w == 0) {
            key = (lane < 8) ? s_wk[lane] : 0;
            xy  = (lane < 8) ? s_wxy[lane] : 0;
            bz  = (lane < 8) ? s_wz[lane] : 0.0f;
#pragma unroll
            for (int o = 4; o; o >>= 1) {
                ull  ok = __shfl_xor_sync(0xffffffffu, key, o);
                ull  oxy= __shfl_xor_sync(0xffffffffu, xy,  o);
                float oz= __shfl_xor_sync(0xffffffffu, bz,  o);
                if (ok > key) { key = ok; xy = oxy; bz = oz; }
            }
            if (lane == 0) {
                uint32_t la = smem_u32(&s_ex[p][0]);
                asm volatile("st.shared.v2.b64 [%0], {%1, %2};" :: "r"(la), "l"(key), "l"(xy) : "memory");
                asm volatile("st.shared.b32 [%0], %1;" :: "r"(smem_u32(&s_exz[p])), "f"(bz) : "memory");
            }
        }
        asm volatile("barrier.cluster.arrive.aligned;" ::: "memory");
        asm volatile("barrier.cluster.wait.aligned;"   ::: "memory");
        ull kk = 0, kxy = 0; float kz = 0.0f;
        if (lane < CLU) {
            uint32_t la = smem_u32(&s_ex[p][0]), ra;
            asm volatile("mapa.shared::cluster.u32 %0, %1, %2;" : "=r"(ra) : "r"(la), "r"((uint32_t)lane));
            asm volatile("ld.shared::cluster.v2.b64 {%0, %1}, [%2];" : "=l"(kk), "=l"(kxy) : "r"(ra));
        } else if (lane < 2*CLU) {
            uint32_t la = smem_u32(&s_exz[p]), ra;
            asm volatile("mapa.shared::cluster.u32 %0, %1, %2;" : "=r"(ra) : "r"(la), "r"((uint32_t)(lane - CLU)));
            asm volatile("ld.shared::cluster.b32 %0, [%1];" : "=f"(kz) : "r"(ra));
        }
        kz = __shfl_down_sync(0xffffffffu, kz, CLU);
#pragma unroll
        for (int o = 4; o; o >>= 1) {
            ull  ok = __shfl_xor_sync(0xffffffffu, kk,  o);
            ull  oxy= __shfl_xor_sync(0xffffffffu, kxy, o);
            float oz= __shfl_xor_sync(0xffffffffu, kz,  o);
            if (ok > kk) { kk = ok; kxy = oxy; kz = oz; }
        }
        kk  = __shfl_sync(0xffffffffu, kk,  0);
        kxy = __shfl_sync(0xffffffffu, kxy, 0);
        kz  = __shfl_sync(0xffffffffu, kz,  0);
        if (rank == 0 && t == 0) {
            fidx[(size_t)b*2048 + j] = 16383 - (int)(kk & 0x3FFFu);
            float wx, wy; upkxy(kxy, wx, wy);
            float* o = nxyz + ((size_t)b*2048 + j)*3;
            o[0] = wx; o[1] = wy; o[2] = kz;
            st_rel(&prog[b], j + 1);
        }
        upkxy(kxy, cx, cy); cz = kz;
    }
}

// ============ bq1 item: centers 8q..8q+7, SMEM-tiled cloud ============
#define BQ_CH 2048
__device__ __forceinline__ void bq1_item(const float4* __restrict__ pk, const float* __restrict__ nxyz,
                                         int* __restrict__ nidx, int q, float4* sp)
{
    const int t = threadIdx.x, w = t >> 5, lane = t & 31;
    const int gw = q * 8 + w;
    const int b = gw >> 11;
    const float4* xb = pk + (size_t)b * 16384;
    const float nx = nxyz[gw*3+0], ny = nxyz[gw*3+1], nz = nxyz[gw*3+2];
    const float sn = (nx*nx + ny*ny) + nz*nz;
    int* out = nidx + (size_t)gw * 64;

    int cnt = 0, first = -1;
    bool donef = false;
    for (int base = 0; base < 16384; base += BQ_CH) {
        __syncthreads();
#pragma unroll
        for (int qq = 0; qq < BQ_CH/256; qq++)
            sp[t + qq*256] = xb[base + t + qq*256];
        __syncthreads();
        if (donef) continue;
        for (int inner = 0; inner < BQ_CH; inner += 32) {
            float4 p = sp[inner + lane];
            float dot = (nx*p.x + ny*p.y) + nz*p.z;
            bool in = ((sn + p.w) - 2.0f*dot) < 0.04f;
            unsigned m = __ballot_sync(0xffffffffu, in);
            if (in) {
                int pos = cnt + __popc(m & ((1u << lane) - 1u));
                if (pos < 64) out[pos] = base + inner + lane;
            }
            if (first < 0 && m) first = base + inner + __ffs(m) - 1;
            cnt += __popc(m);
            if (cnt >= 64) { donef = true; break; }
        }
    }
    for (int p = cnt + lane; p < 64; p += 32) out[p] = first;
}

// ============ sa1 item: 2 centers, 256 thr = 2x128 halves, weights preloaded in sW ============
// sW layout: W0@0(192) B0@192(64) B1@256(64) B2@320(128) W1@448(4096) -> 4544
// per-half scratch at sm+4544+half*8384: R(192) H0(4096) H1(4096)
#define MEGA_SMEM 21312
__device__ __forceinline__ void sa1_item(const float* __restrict__ xyz, const float* __restrict__ nxyz,
                const int* __restrict__ nidx, const float* __restrict__ w2,
                float* __restrict__ feats, int ctr0, float* sm)
{
    float* sW0 = sm;
    float* sB0 = sm + 192;
    float* sB1 = sm + 256;
    float* sB2 = sm + 320;
    float* sW1 = sm + 448;
    const int t = threadIdx.x, half = t >> 7, ht = t & 127;
    const int ctr = ctr0 + half;
    const int b = ctr >> 11;
    float* sR  = sm + 4544 + half*8384;
    float* sH0 = sR + 192;
    float* sH1 = sH0 + 4096;

    if (ht < 64) {
        int id = nidx[(size_t)ctr*64 + ht];
        const float* p = xyz + ((size_t)(b << 14) + id)*3;
        sR[ht*3+0] = (p[0] - nxyz[ctr*3+0]) / 0.2f;
        sR[ht*3+1] = (p[1] - nxyz[ctr*3+1]) / 0.2f;
        sR[ht*3+2] = (p[2] - nxyz[ctr*3+2]) / 0.2f;
    }
    __syncthreads();

    {
        int n = ht & 63, hh = ht >> 6;
        float rx = sR[n*3+0], ry = sR[n*3+1], rz = sR[n*3+2];
#pragma unroll 8
        for (int cc = 0; cc < 32; cc++) {
            int c = hh*32 + cc;
            float v = sB0[c] + rx*sW0[c] + ry*sW0[64+c] + rz*sW0[128+c];
            sH0[c*64 + n] = fmaxf(v, 0.0f);
        }
    }
    __syncthreads();

    const int ng = ht & 15, cg = ht >> 4;
    float acc[32];

#pragma unroll
    for (int i = 0; i < 4; i++)
#pragma unroll
        for (int jj = 0; jj < 8; jj++) acc[i*8+jj] = sB1[8*cg + jj];
#pragma unroll 8
    for (int k = 0; k < 64; k++) {
        float4 a = *(const float4*)&sH0[k*64 + 4*ng];
        float4 u = *(const float4*)&sW1[k*64 + 8*cg];
        float4 v = *(const float4*)&sW1[k*64 + 8*cg + 4];
        float av[4] = {a.x, a.y, a.z, a.w};
        float bv[8] = {u.x, u.y, u.z, u.w, v.x, v.y, v.z, v.w};
#pragma unroll
        for (int i = 0; i < 4; i++)
#pragma unroll
            for (int jj = 0; jj < 8; jj++) acc[i*8+jj] += av[i]*bv[jj];
    }
#pragma unroll
    for (int jj = 0; jj < 8; jj++) {
        float4 o;
        o.x = fmaxf(acc[0*8+jj], 0.0f);
        o.y = fmaxf(acc[1*8+jj], 0.0f);
        o.z = fmaxf(acc[2*8+jj], 0.0f);
        o.w = fmaxf(acc[3*8+jj], 0.0f);
        *(float4*)&sH1[(8*cg+jj)*64 + 4*ng] = o;
    }
    __syncthreads();

#pragma unroll 1
    for (int pass = 0; pass < 2; pass++) {
        int c0 = pass*64 + 8*cg;
#pragma unroll
        for (int i = 0; i < 4; i++)
#pragma unroll
            for (int jj = 0; jj < 8; jj++) acc[i*8+jj] = sB2[c0 + jj];
#pragma unroll 4
        for (int k = 0; k < 64; k++) {
            float4 a = *(const float4*)&sH1[k*64 + 4*ng];
            float4 u = *(const float4*)&w2[k*128 + c0];
            float4 v = *(const float4*)&w2[k*128 + c0 + 4];
            float av[4] = {a.x, a.y, a.z, a.w};
            float bv[8] = {u.x, u.y, u.z, u.w, v.x, v.y, v.z, v.w};
#pragma unroll
            for (int i = 0; i < 4; i++)
#pragma unroll
                for (int jj = 0; jj < 8; jj++) acc[i*8+jj] += av[i]*bv[jj];
        }
#pragma unroll
        for (int jj = 0; jj < 8; jj++) {
            float m = fmaxf(fmaxf(fmaxf(acc[0*8+jj], 0.0f), fmaxf(acc[1*8+jj], 0.0f)),
                            fmaxf(fmaxf(acc[2*8+jj], 0.0f), fmaxf(acc[3*8+jj], 0.0f)));
#pragma unroll
            for (int off = 8; off; off >>= 1)
                m = fmaxf(m, __shfl_xor_sync(0xffffffffu, m, off));
            if (ng == 0) feats[(size_t)ctr*128 + c0 + jj] = m;
        }
    }
}

// ============ FPS stages 2-4 device body (R12-proven) ============
template<int BLK, int P>
__device__ __forceinline__ void fps_reg_dev(const float* __restrict__ xyz, int npoint,
                                            int* __restrict__ fidx, float* __restrict__ nxyz,
                                            int b, float* sm)
{
    const int N = BLK * P;
    float* sx = sm; float* sy = sm + N; float* sz = sm + 2*N;
    __shared__ float rv[32];
    __shared__ int   ri[32];
    __shared__ float s_cxyz[3];

    const int t = threadIdx.x;
    const float* base = xyz + (size_t)b * N * 3;
    float px[P], py[P], pz[P], dst[P];
#pragma unroll
    for (int k = 0; k < P; k++) {
        int i = t + k*BLK;
        px[k] = base[i*3+0]; py[k] = base[i*3+1]; pz[k] = base[i*3+2];
        sx[i] = px[k]; sy[i] = py[k]; sz[i] = pz[k];
        dst[k] = 1e10f;
    }
    if (t == 0) {
        s_cxyz[0] = px[0]; s_cxyz[1] = py[0]; s_cxyz[2] = pz[0];
        fidx[(size_t)b*npoint] = 0;
        float* o = nxyz + (size_t)b*npoint*3;
        o[0] = px[0]; o[1] = py[0]; o[2] = pz[0];
    }
    __syncthreads();

    for (int j = 1; j < npoint; j++) {
        const float cx = s_cxyz[0], cy = s_cxyz[1], cz = s_cxyz[2];
        float best = -1.0f; int bi = 0x7fffffff;
#pragma unroll
        for (int k = 0; k < P; k++) {
            float dx = px[k]-cx, dy = py[k]-cy, dz = pz[k]-cz;
            float nd = fminf(dst[k], dx*dx + dy*dy + dz*dz);
            dst[k] = nd;
            if (nd > best) { best = nd; bi = t + k*BLK; }
        }
#pragma unroll
        for (int off = 16; off; off >>= 1) {
            float ov = __shfl_down_sync(0xffffffffu, best, off);
            int   oi = __shfl_down_sync(0xffffffffu, bi,   off);
            if (ov > best || (ov == best && oi < bi)) { best = ov; bi = oi; }
        }
        int w = t >> 5;
        if ((t & 31) == 0) { rv[w] = best; ri[w] = bi; }
        __syncthreads();
        if (t < 32) {
            const int nw = BLK / 32;
            float v  = (t < nw) ? rv[t] : -1.0f;
            int   i2 = (t < nw) ? ri[t] : 0x7fffffff;
#pragma unroll
            for (int off = 16; off; off >>= 1) {
                float ov = __shfl_down_sync(0xffffffffu, v,  off);
                int   oi = __shfl_down_sync(0xffffffffu, i2, off);
                if (ov > v || (ov == v && oi < i2)) { v = ov; i2 = oi; }
            }
            if (t == 0) {
                fidx[(size_t)b*npoint + j] = i2;
                float wx = sx[i2], wy = sy[i2], wz = sz[i2];
                s_cxyz[0] = wx; s_cxyz[1] = wy; s_cxyz[2] = wz;
                float* o = nxyz + ((size_t)b*npoint + j)*3;
                o[0] = wx; o[1] = wy; o[2] = wz;
            }
        }
        __syncthreads();
    }
}

// ================== MEGA2: bounded-residency persistent overlap ==================
// grid = 128 (16 clusters of 8). bids 0-31 fps1 | 32-35 fps2 | 36-127 consumers (92).
__global__ __launch_bounds__(256) __cluster_dims__(CLU, 1, 1)
void mega2(const float* pc, const float4* pk4, int* fidx, int* fidx2,
           float* nx1, float* nx2, int* nidx1,
           const float* w0, const float* b0, const float* w1, const float* b1,
           const float* w2, const float* b2, float* f1, int* prog, int* bqdone)
{
    extern __shared__ float smf[];
    const int bid = blockIdx.x;
    const int t = threadIdx.x;
    if (bid < 32) {
        fps1_dev(pc, fidx, nx1, bid, prog);
        return;
    }
    if (bid < 36) {
        int b = bid - 32;
        if (t == 0) { while (ld_acq(&prog[b]) < 2048) __nanosleep(1000); }
        __syncthreads();
        fps_reg_dev<256,8>(nx1, 1024, fidx2, nx2, b, smf);
        return;
    }
    // consumer: preload weights once
    for (int i = t; i < 192;  i += 256) smf[i] = w0[i];
    if (t < 64)  { smf[192+t] = b0[t]; smf[256+t] = b1[t]; }
    if (t < 128) smf[320+t] = b2[t];
    for (int i = t; i < 4096; i += 256) smf[448+i] = w1[i];
    __syncthreads();
    const int c = bid - 36;
    const int C = 92;
    for (int s = c; s < 5120; s += C) {
        int q = s / 5, r = s - q*5;
        if (r == 0) {
            int b = (q*8) >> 11;
            int need = ((q*8 + 7) & 2047) + 1;
            if (t == 0) { while (ld_acq(&prog[b]) < need) __nanosleep(500); }
            __syncthreads();
            bq1_item(pk4, nx1, nidx1, q, (float4*)(smf + 4544));
            __threadfence();
            __syncthreads();
            if (t == 0) st_rel(&bqdone[q], 1);
        } else {
            int i = 4*q + (r - 1);
            if (t == 0) { while (ld_acq(&bqdone[q]) == 0) __nanosleep(500); }
            __syncthreads();
            sa1_item(pc, nx1, nidx1, w2, f1, 2*i, smf);
            __syncthreads();
        }
    }
}

__global__ void zero_flags(int* prog, int* bqdone)
{
    int i = blockIdx.x*blockDim.x + threadIdx.x;
    if (i < NB) prog[i] = 0;
    if (i < 1024) bqdone[i] = 0;
}

__global__ void pack4_kernel(const float* __restrict__ xyz, float4* __restrict__ pk, int total)
{
    int i = blockIdx.x*blockDim.x + threadIdx.x;
    if (i >= total) return;
    float x = xyz[i*3+0], y = xyz[i*3+1], z = xyz[i*3+2];
    pk[i] = make_float4(x, y, z, (x*x + y*y) + z*z);
}

// ============ ball query (SoA, warp-per-center) ============
__device__ __forceinline__ void bq_dev(const float* __restrict__ xyz, const float* __restrict__ nxyz,
                                       int* __restrict__ nidx, int S, int N, int nsample,
                                       float r2, int gw)
{
    int lane = threadIdx.x & 31;
    int b = gw / S;
    const float* xb = xyz + (size_t)b * N * 3;
    float nx = nxyz[gw*3+0], ny = nxyz[gw*3+1], nz = nxyz[gw*3+2];
    float sn = (nx*nx + ny*ny) + nz*nz;
    int* out = nidx + (size_t)gw * nsample;

    int cnt = 0, first = -1;
    for (int base = 0; base < N; base += 32) {
        int j = base + lane;
        float x = xb[j*3+0], y = xb[j*3+1], z = xb[j*3+2];
        float sxx = (x*x + y*y) + z*z;
        float dot = (nx*x + ny*y) + nz*z;
        bool in = ((sn + sxx) - 2.0f*dot) < r2;
        unsigned m = __ballot_sync(0xffffffffu, in);
        if (in) {
            int pos = cnt + __popc(m & ((1u << lane) - 1u));
            if (pos < nsample) out[pos] = j;
        }
        if (first < 0 && m) first = base + __ffs(m) - 1;
        cnt += __popc(m);
        if (cnt >= nsample) break;
    }
    for (int p = cnt + lane; p < nsample; p += 32) out[p] = first;
}

// ============ GEMM device bodies (R12-proven) ============
__device__ __forceinline__ void gemm128_dev(const float* __restrict__ A, const float* __restrict__ W,
             const float* __restrict__ bias, float* __restrict__ Y,
             int M, int N, int K, int bxv, int byv)
{
    __shared__ __align__(16) float As[8][128];
    __shared__ __align__(16) float Bs[8][128];
    const int bm = byv * 128;
    const int bn = bxv * 128;
    const int t  = threadIdx.x;
    const int ty = t >> 4, tx = t & 15;
    float acc[8][8];
#pragma unroll
    for (int i = 0; i < 8; i++)
#pragma unroll
        for (int j = 0; j < 8; j++) acc[i][j] = 0.0f;

    const int abr = t >> 5;
    const int abc = (t & 31) * 4;

    float ra[4]; float4 rb;
#pragma unroll
    for (int q = 0; q < 4; q++) {
        int e = t*4 + q;
        int ar = e >> 3, ac = e & 7;
        ra[q] = (ac < K) ? A[(size_t)(bm + ar)*K + ac] : 0.0f;
    }
    rb = (abr < K) ? *(const float4*)&W[(size_t)abr*N + bn + abc]
                   : make_float4(0.f,0.f,0.f,0.f);

    for (int k0 = 0; k0 < K; k0 += 8) {
#pragma unroll
        for (int q = 0; q < 4; q++) {
            int e = t*4 + q;
            As[e & 7][e >> 3] = ra[q];
        }
        *(float4*)&Bs[abr][abc] = rb;
        __syncthreads();
        if (k0 + 8 < K) {
#pragma unroll
            for (int q = 0; q < 4; q++) {
                int e = t*4 + q;
                int ar = e >> 3, ac = e & 7;
                int kk = k0 + 8 + ac;
                ra[q] = (kk < K) ? A[(size_t)(bm + ar)*K + kk] : 0.0f;
            }
            int kk = k0 + 8 + abr;
            rb = (kk < K) ? *(const float4*)&W[(size_t)kk*N + bn + abc]
                          : make_float4(0.f,0.f,0.f,0.f);
        }
#pragma unroll
        for (int kk = 0; kk < 8; kk++) {
            float4 a0 = *(const float4*)&As[kk][ty*8];
            float4 a1 = *(const float4*)&As[kk][ty*8 + 4];
            float4 b0 = *(const float4*)&Bs[kk][tx*8];
            float4 b1 = *(const float4*)&Bs[kk][tx*8 + 4];
            float av[8] = {a0.x, a0.y, a0.z, a0.w, a1.x, a1.y, a1.z, a1.w};
            float bv[8] = {b0.x, b0.y, b0.z, b0.w, b1.x, b1.y, b1.z, b1.w};
#pragma unroll
            for (int i = 0; i < 8; i++)
#pragma unroll
                for (int j = 0; j < 8; j++) acc[i][j] += av[i]*bv[j];
        }
        __syncthreads();
    }
    float4 bb0 = *(const float4*)&bias[bn + tx*8];
    float4 bb1 = *(const float4*)&bias[bn + tx*8 + 4];
    float bv[8] = {bb0.x, bb0.y, bb0.z, bb0.w, bb1.x, bb1.y, bb1.z, bb1.w};
#pragma unroll
    for (int i = 0; i < 8; i++) {
        size_t row = (size_t)(bm + ty*8 + i);
        float4 o0, o1;
        o0.x = fmaxf(acc[i][0]+bv[0], 0.f); o0.y = fmaxf(acc[i][1]+bv[1], 0.f);
        o0.z = fmaxf(acc[i][2]+bv[2], 0.f); o0.w = fmaxf(acc[i][3]+bv[3], 0.f);
        o1.x = fmaxf(acc[i][4]+bv[4], 0.f); o1.y = fmaxf(acc[i][5]+bv[5], 0.f);
        o1.z = fmaxf(acc[i][6]+bv[6], 0.f); o1.w = fmaxf(acc[i][7]+bv[7], 0.f);
        *(float4*)&Y[row*N + bn + tx*8]     = o0;
        *(float4*)&Y[row*N + bn + tx*8 + 4] = o1;
    }
}

__device__ __forceinline__ void gemm128g_dev(const float* __restrict__ xyz, const float* __restrict__ nxyz,
              const int* __restrict__ nidx, const float* __restrict__ feats,
              const float* __restrict__ W, const float* __restrict__ bias,
              float* __restrict__ Y, int M, int N, int K,
              int ns, int npts, int C, float radius, int rows_pb, int bxv, int byv)
{
    __shared__ __align__(16) float Asg[8][128];
    __shared__ __align__(16) float Bsg[8][128];
    const int bm = byv * 128;
    const int bn = bxv * 128;
    const int t  = threadIdx.x;
    const int ty = t >> 4, tx = t & 15;
    float acc[8][8];
#pragma unroll
    for (int i = 0; i < 8; i++)
#pragma unroll
        for (int j = 0; j < 8; j++) acc[i][j] = 0.0f;

    const int ar  = (t*4) >> 3;
    const int ac0 = (t*4) & 7;
    const int row = bm + ar;
    const int ci  = row / ns;
    const int b   = row / rows_pb;
    const int id  = nidx[row];
    const float* pt = xyz + ((size_t)b*npts + id)*3;
    const float* fr = feats + ((size_t)b*npts + id)*C;
    float rel[3];
#pragma unroll
    for (int cc = 0; cc < 3; cc++) rel[cc] = (pt[cc] - nxyz[ci*3+cc]) / radius;

    const int abr = t >> 5;
    const int abc = (t & 31) * 4;

    float ra[4]; float4 rb;
#pragma unroll
    for (int q = 0; q < 4; q++) {
        int kk = ac0 + q;
        ra[q] = (kk < 3) ? rel[kk] : ((kk < K) ? fr[kk-3] : 0.0f);
    }
    rb = (abr < K) ? *(const float4*)&W[(size_t)abr*N + bn + abc]
                   : make_float4(0.f,0.f,0.f,0.f);

    for (int k0 = 0; k0 < K; k0 += 8) {
#pragma unroll
        for (int q = 0; q < 4; q++)
            Asg[ac0 + q][ar] = ra[q];
        *(float4*)&Bsg[abr][abc] = rb;
        __syncthreads();
        if (k0 + 8 < K) {
#pragma unroll
            for (int q = 0; q < 4; q++) {
                int kk = k0 + 8 + ac0 + q;
                ra[q] = (kk < 3) ? rel[kk] : ((kk < K) ? fr[kk-3] : 0.0f);
            }
            int kk = k0 + 8 + abr;
            rb = (kk < K) ? *(const float4*)&W[(size_t)kk*N + bn + abc]
                          : make_float4(0.f,0.f,0.f,0.f);
        }
#pragma unroll
        for (int kk = 0; kk < 8; kk++) {
            float4 a0 = *(const float4*)&Asg[kk][ty*8];
            float4 a1 = *(const float4*)&Asg[kk][ty*8 + 4];
            float4 b0 = *(const float4*)&Bsg[kk][tx*8];
            float4 b1 = *(const float4*)&Bsg[kk][tx*8 + 4];
            float av[8] = {a0.x, a0.y, a0.z, a0.w, a1.x, a1.y, a1.z, a1.w};
            float bv[8] = {b0.x, b0.y, b0.z, b0.w, b1.x, b1.y, b1.z, b1.w};
#pragma unroll
            for (int i = 0; i < 8; i++)
#pragma unroll
                for (int j = 0; j < 8; j++) acc[i][j] += av[i]*bv[j];
        }
        __syncthreads();
    }
    float4 bb0 = *(const float4*)&bias[bn + tx*8];
    float4 bb1 = *(const float4*)&bias[bn + tx*8 + 4];
    float bv[8] = {bb0.x, bb0.y, bb0.z, bb0.w, bb1.x, bb1.y, bb1.z, bb1.w};
#pragma unroll
    for (int i = 0; i < 8; i++) {
        size_t orow = (size_t)(bm + ty*8 + i);
        float4 o0, o1;
        o0.x = fmaxf(acc[i][0]+bv[0], 0.f); o0.y = fmaxf(acc[i][1]+bv[1], 0.f);
        o0.z = fmaxf(acc[i][2]+bv[2], 0.f); o0.w = fmaxf(acc[i][3]+bv[3], 0.f);
        o1.x = fmaxf(acc[i][4]+bv[4], 0.f); o1.y = fmaxf(acc[i][5]+bv[5], 0.f);
        o1.z = fmaxf(acc[i][6]+bv[6], 0.f); o1.w = fmaxf(acc[i][7]+bv[7], 0.f);
        *(float4*)&Y[orow*N + bn + tx*8]     = o0;
        *(float4*)&Y[orow*N + bn + tx*8 + 4] = o1;
    }
}

__global__ __launch_bounds__(256)
void gemm128(const float* A, const float* W, const float* bias, float* Y, int M, int N, int K)
{ gemm128_dev(A, W, bias, Y, M, N, K, blockIdx.x, blockIdx.y); }

__global__ __launch_bounds__(256)
void gemm128g(const float* xyz, const float* nxyz, const int* nidx, const float* feats,
              const float* W, const float* bias, float* Y, int M, int N, int K,
              int ns, int npts, int C, float radius, int rows_pb)
{ gemm128g_dev(xyz, nxyz, nidx, feats, W, bias, Y, M, N, K, ns, npts, C, radius, rows_pb, blockIdx.x, blockIdx.y); }

// ============ GEMM + bias + relu + fused maxpool ============
template<int NS>
__global__ __launch_bounds__(256)
void gemm128_mp(const float* __restrict__ A, const float* __restrict__ W,
                const float* __restrict__ bias, float* __restrict__ out,
                int M, int N, int K)
{
    __shared__ __align__(16) float As[8][128];
    __shared__ __align__(16) float Bs[8][128];
    __shared__ float red[16][136];
    const int bm = blockIdx.y * 128;
    const int bn = blockIdx.x * 128;
    const int t  = threadIdx.x;
    const int ty = t >> 4, tx = t & 15;
    float acc[8][8];
#pragma unroll
    for (int i = 0; i < 8; i++)
#pragma unroll
        for (int j = 0; j < 8; j++) acc[i][j] = 0.0f;

    const int abr = t >> 5;
    const int abc = (t & 31) * 4;

    float ra[4]; float4 rb;
#pragma unroll
    for (int q = 0; q < 4; q++) {
        int e = t*4 + q;
        int ar = e >> 3, ac = e & 7;
        ra[q] = (ac < K) ? A[(size_t)(bm + ar)*K + ac] : 0.0f;
    }
    rb = (abr < K) ? *(const float4*)&W[(size_t)abr*N + bn + abc]
                   : make_float4(0.f,0.f,0.f,0.f);

    for (int k0 = 0; k0 < K; k0 += 8) {
#pragma unroll
        for (int q = 0; q < 4; q++) {
            int e = t*4 + q;
            As[e & 7][e >> 3] = ra[q];
        }
        *(float4*)&Bs[abr][abc] = rb;
        __syncthreads();
        if (k0 + 8 < K) {
#pragma unroll
            for (int q = 0; q < 4; q++) {
                int e = t*4 + q;
                int ar = e >> 3, ac = e & 7;
                int kk = k0 + 8 + ac;
                ra[q] = (kk < K) ? A[(size_t)(bm + ar)*K + kk] : 0.0f;
            }
            int kk = k0 + 8 + abr;
            rb = (kk < K) ? *(const float4*)&W[(size_t)kk*N + bn + abc]
                          : make_float4(0.f,0.f,0.f,0.f);
        }
#pragma unroll
        for (int kk = 0; kk < 8; kk++) {
            float4 a0 = *(const float4*)&As[kk][ty*8];
            float4 a1 = *(const float4*)&As[kk][ty*8 + 4];
            float4 b0 = *(const float4*)&Bs[kk][tx*8];
            float4 b1 = *(const float4*)&Bs[kk][tx*8 + 4];
            float av[8] = {a0.x, a0.y, a0.z, a0.w, a1.x, a1.y, a1.z, a1.w};
            float bv[8] = {b0.x, b0.y, b0.z, b0.w, b1.x, b1.y, b1.z, b1.w};
#pragma unroll
            for (int i = 0; i < 8; i++)
#pragma unroll
                for (int j = 0; j < 8; j++) acc[i][j] += av[i]*bv[j];
        }
        __syncthreads();
    }
    float4 bb0 = *(const float4*)&bias[bn + tx*8];
    float4 bb1 = *(const float4*)&bias[bn + tx*8 + 4];
    float bv[8] = {bb0.x, bb0.y, bb0.z, bb0.w, bb1.x, bb1.y, bb1.z, bb1.w};
#pragma unroll
    for (int j = 0; j < 8; j++) {
        float m = fmaxf(acc[0][j] + bv[j], 0.0f);
#pragma unroll
        for (int i = 1; i < 8; i++) m = fmaxf(m, fmaxf(acc[i][j] + bv[j], 0.0f));
        red[ty][tx*8 + j] = m;
    }
    __syncthreads();
    const int g = NS / 8;
    if ((ty % g) == 0) {
        int center = (bm + ty*8) / NS;
#pragma unroll
        for (int j = 0; j < 8; j++) {
            float m = red[ty][tx*8 + j];
#pragma unroll
            for (int r = 1; r < g; r++) m = fmaxf(m, red[ty + r][tx*8 + j]);
            out[(size_t)center*N + bn + tx*8 + j] = m;
        }
    }
}

// ================== fat combo kernels (R12-proven structure) ==================
// L4 (128 thr): [0,1024) bq2 (4 warps/blk) | [1024,1028) fps3
__global__ __launch_bounds__(128)
void combo_L4(const float* nx1, const float* nx2, int* nidx2, int* fidx, float* nx3)
{
    extern __shared__ float smf[];
    int bid = blockIdx.x;
    if (bid < 1024) {
        int gw = bid*4 + (threadIdx.x >> 5);
        bq_dev(nx1, nx2, nidx2, 1024, 2048, 32, 0.16f, gw);
    } else {
        fps_reg_dev<128,8>(nx2, 512, fidx, nx3, bid - 1024, smf);
    }
}

// L5 (256 thr): [0,1024) gemm_g2 | [1024,1280) bq3 (8 warps/blk) | [1280,1284) fps4
__global__ __launch_bounds__(256)
void combo_L5(const float* nx1, const float* nx2, const int* nidx2, const float* f1,
              const float* w20, const float* b20, float* YA,
              const float* nx3, int* nidx3, int* fidx, float* nx4)
{
    extern __shared__ float smf[];
    int bid = blockIdx.x;
    if (bid < 1024) {
        gemm128g_dev(nx1, nx2, nidx2, f1, w20, b20, YA, 131072, 128, 131, 32, 2048, 128, 0.4f, 32768, 0, bid);
    } else if (bid < 1280) {
        int gw = (bid - 1024)*8 + (threadIdx.x >> 5);
        bq_dev(nx2, nx3, nidx3, 512, 1024, 16, 0.36f, gw);
    } else {
        fps_reg_dev<256,2>(nx3, 256, fidx, nx4, bid - 1280, smf);
    }
}

// L6 (256 thr): [0,1024) gemm mid-2 | [1024,1152) bq4 (8 warps/blk)
__global__ __launch_bounds__(256)
void combo_L6(const float* YA, const float* w21, const float* b21, float* YB,
              const float* nx3, const float* nx4, int* nidx4)
{
    int bid = blockIdx.x;
    if (bid < 1024) {
        gemm128_dev(YA, w21, b21, YB, 131072, 128, 128, 0, bid);
    } else {
        int gw = (bid - 1024)*8 + (threadIdx.x >> 5);
        bq_dev(nx3, nx4, nidx4, 256, 512, 8, 1.44f, gw);
    }
}

static inline int cdiv(int a, int b) { return (a + b - 1) / b; }

extern "C" void kernel_launch(void* const* d_in, const int* in_sizes, int n_in,
                              void* d_out, int out_size)
{
    (void)in_sizes; (void)n_in; (void)out_size;
    const float* pc  = (const float*)d_in[0];
    const float* w10 = (const float*)d_in[1],  *b10 = (const float*)d_in[2];
    const float* w11 = (const float*)d_in[3],  *b11 = (const float*)d_in[4];
    const float* w12 = (const float*)d_in[5],  *b12 = (const float*)d_in[6];
    const float* w20 = (const float*)d_in[7],  *b20 = (const float*)d_in[8];
    const float* w21 = (const float*)d_in[9],  *b21 = (const float*)d_in[10];
    const float* w22 = (const float*)d_in[11], *b22 = (const float*)d_in[12];
    const float* w30 = (const float*)d_in[13], *b30 = (const float*)d_in[14];
    const float* w31 = (const float*)d_in[15], *b31 = (const float*)d_in[16];
    const float* w32 = (const float*)d_in[17], *b32 = (const float*)d_in[18];
    const float* w40 = (const float*)d_in[19], *b40 = (const float*)d_in[20];
    const float* w41 = (const float*)d_in[21], *b41 = (const float*)d_in[22];
    const float* w42 = (const float*)d_in[23], *b42 = (const float*)d_in[24];

    float *nx1, *nx2, *nx3, *f1, *f2, *f3, *YA, *YB;
    float4 *pk4;
    int *fidx, *fidx2, *nidx, *prog, *bqdone;
    cudaGetSymbolAddress((void**)&nx1,  g_nx1);
    cudaGetSymbolAddress((void**)&nx2,  g_nx2);
    cudaGetSymbolAddress((void**)&nx3,  g_nx3);
    cudaGetSymbolAddress((void**)&f1,   g_f1);
    cudaGetSymbolAddress((void**)&f2,   g_f2);
    cudaGetSymbolAddress((void**)&f3,   g_f3);
    cudaGetSymbolAddress((void**)&YA,   g_YA);
    cudaGetSymbolAddress((void**)&YB,   g_YB);
    cudaGetSymbolAddress((void**)&fidx, g_fidx);
    cudaGetSymbolAddress((void**)&fidx2, g_fidx2);
    cudaGetSymbolAddress((void**)&nidx, g_nidx);
    cudaGetSymbolAddress((void**)&pk4,  g_pk4);
    cudaGetSymbolAddress((void**)&prog, g_fps_prog);
    cudaGetSymbolAddress((void**)&bqdone, g_bqdone);
    int* nidx1 = nidx;
    int* nidx2 = nidx + 524288;
    int* nidx3 = nidx + 655360;
    int* nidx4 = nidx + 688128;

    cudaFuncSetAttribute((const void*)mega2,
                         cudaFuncAttributeMaxDynamicSharedMemorySize, MEGA_SMEM*4);

    float* out = (float*)d_out;
    float* nx4 = out;          // [4,256,3]
    float* f4  = out + 3072;   // [4,256,512]

    zero_flags<<<4, 256>>>(prog, bqdone);
    pack4_kernel<<<cdiv(NB*16384,256),256>>>(pc, pk4, NB*16384);
    mega2<<<128, 256, MEGA_SMEM*4>>>(pc, pk4, fidx, fidx2, nx1, nx2, nidx1,
                                     w10,b10,w11,b11,w12,b12, f1, prog, bqdone);
    combo_L4<<<1028, 128, 3*1024*4>>>(nx1, nx2, nidx2, fidx, nx3);
    combo_L5<<<1284, 256, 6144>>>(nx1, nx2, nidx2, f1, w20, b20, YA, nx3, nidx3, fidx, nx4);
    combo_L6<<<1152, 256>>>(YA, w21, b21, YB, nx3, nx4, nidx4);
    gemm128_mp<32><<<dim3(2, 1024), 256>>>(YB, w22, b22, f2, 131072, 256, 128);

    // Stage 3 MLP
    gemm128g<<<dim3(2, 256), 256>>>(nx2, nx3, nidx3, f2, w30, b30, YA, 32768, 256, 259, 16, 1024, 256, 0.6f, 8192);
    gemm128<<<dim3(2, 256), 256>>>(YA, w31, b31, YB, 32768, 256, 256);
    gemm128_mp<16><<<dim3(4, 256), 256>>>(YB, w32, b32, f3, 32768, 512, 256);

    // Stage 4 MLP
    gemm128g<<<dim3(4, 64), 256>>>(nx3, nx4, nidx4, f3, w40, b40, YA, 8192, 512, 515, 8, 512, 512, 1.2f, 2048);
    gemm128<<<dim3(4, 64), 256>>>(YA, w41, b41, YB, 8192, 512, 512);
    gemm128_mp<8><<<dim3(4, 64), 256>>>(YB, w42, b42, f4, 8192, 512, 512);
}

// round 15
// speedup vs baseline: 1.5174x; 1.5174x over previous
#include <cuda_runtime.h>
#include <cstdint>

#define NB 4
typedef unsigned long long ull;

// ---------------- static device scratch ----------------
__device__ float g_nx1[NB*2048*3];
__device__ float g_nx2[NB*1024*3];
__device__ float g_nx3[NB*512*3];
__device__ float g_f1[NB*2048*128];
__device__ float g_f2[NB*1024*256];
__device__ float g_f3[NB*512*512];
__device__ int   g_fidx[NB*2048];
__device__ int   g_nidx[720896];     // nidx1@0 | nidx2@524288 | nidx3@655360 | nidx4@688128
__device__ float g_YA[33554432];
__device__ float g_YB[16777216];
__device__ float4 g_pk4[NB*16384];

__device__ __forceinline__ uint32_t smem_u32(const void* p) {
    uint32_t a;
    asm("{ .reg .u64 t; cvta.to.shared.u64 t, %1; cvt.u32.u64 %0, t; }" : "=r"(a) : "l"(p));
    return a;
}
__device__ __forceinline__ ull pkxy(float x, float y) {
    ull r; asm("mov.b64 %0, {%1, %2};" : "=l"(r) : "f"(x), "f"(y)); return r;
}
__device__ __forceinline__ void upkxy(ull v, float& x, float& y) {
    asm("mov.b64 {%0, %1}, %2;" : "=f"(x), "=f"(y) : "l"(v));
}

// ================== FPS stage 1: 8-CTA cluster, 256 thr, all-warp pull (R12-proven) ==================
#define CLU 8
__global__ __launch_bounds__(256) __cluster_dims__(CLU, 1, 1)
void fps1_cluster(const float* __restrict__ xyz, int* __restrict__ fidx,
                  float* __restrict__ nxyz)
{
    __shared__ ull   s_wk[8];
    __shared__ ull   s_wxy[8];
    __shared__ float s_wz[8];
    __shared__ __align__(16) ull s_ex[2][2];
    __shared__ float s_exz[2];

    const int t = threadIdx.x, lane = t & 31, w = t >> 5;
    uint32_t rank; asm("mov.u32 %0, %%cluster_ctarank;" : "=r"(rank));
    const int b = blockIdx.x / CLU;
    const float* base = xyz + (size_t)b*16384*3;

    float px[8], py[8], pz[8], dd[8];
#pragma unroll
    for (int k = 0; k < 8; k++) {
        int i = (int)rank*2048 + k*256 + t;
        px[k] = base[i*3]; py[k] = base[i*3+1]; pz[k] = base[i*3+2];
        dd[k] = 1e10f;
    }
    float cx = base[0], cy = base[1], cz = base[2];
    if (rank == 0 && t == 0) {
        fidx[(size_t)b*2048] = 0;
        float* o = nxyz + (size_t)b*2048*3;
        o[0] = cx; o[1] = cy; o[2] = cz;
    }

    for (int j = 1; j < 2048; j++) {
        const int p = j & 1;
        float bd = -1.0f, bx = 0, by = 0, bz = 0; int bidx = 0;
#pragma unroll
        for (int k = 0; k < 8; k++) {
            float dx = px[k]-cx, dy = py[k]-cy, dz = pz[k]-cz;
            float nd = fminf(dd[k], dx*dx + dy*dy + dz*dz);
            dd[k] = nd;
            if (nd > bd) { bd = nd; bidx = (int)rank*2048 + k*256 + t; bx = px[k]; by = py[k]; bz = pz[k]; }
        }
        ull key = ((ull)__float_as_uint(bd) << 32) | (ull)(16383 - bidx);
        ull xy  = pkxy(bx, by);
#pragma unroll
        for (int o = 16; o; o >>= 1) {
            ull  ok = __shfl_xor_sync(0xffffffffu, key, o);
            ull  oxy= __shfl_xor_sync(0xffffffffu, xy,  o);
            float oz= __shfl_xor_sync(0xffffffffu, bz,  o);
            if (ok > key) { key = ok; xy = oxy; bz = oz; }
        }
        if (lane == 0) { s_wk[w] = key; s_wxy[w] = xy; s_wz[w] = bz; }
        __syncthreads();
        if (w == 0) {
            key = (lane < 8) ? s_wk[lane] : 0;
            xy  = (lane < 8) ? s_wxy[lane] : 0;
            bz  = (lane < 8) ? s_wz[lane] : 0.0f;
#pragma unroll
            for (int o = 4; o; o >>= 1) {
                ull  ok = __shfl_xor_sync(0xffffffffu, key, o);
                ull  oxy= __shfl_xor_sync(0xffffffffu, xy,  o);
                float oz= __shfl_xor_sync(0xffffffffu, bz,  o);
                if (ok > key) { key = ok; xy = oxy; bz = oz; }
            }
            if (lane == 0) {
                uint32_t la = smem_u32(&s_ex[p][0]);
                asm volatile("st.shared.v2.b64 [%0], {%1, %2};" :: "r"(la), "l"(key), "l"(xy) : "memory");
                asm volatile("st.shared.b32 [%0], %1;" :: "r"(smem_u32(&s_exz[p])), "f"(bz) : "memory");
            }
        }
        asm volatile("barrier.cluster.arrive.aligned;" ::: "memory");
        asm volatile("barrier.cluster.wait.aligned;"   ::: "memory");
        ull kk = 0, kxy = 0; float kz = 0.0f;
        if (lane < CLU) {
            uint32_t la = smem_u32(&s_ex[p][0]), ra;
            asm volatile("mapa.shared::cluster.u32 %0, %1, %2;" : "=r"(ra) : "r"(la), "r"((uint32_t)lane));
            asm volatile("ld.shared::cluster.v2.b64 {%0, %1}, [%2];" : "=l"(kk), "=l"(kxy) : "r"(ra));
        } else if (lane < 2*CLU) {
            uint32_t la = smem_u32(&s_exz[p]), ra;
            asm volatile("mapa.shared::cluster.u32 %0, %1, %2;" : "=r"(ra) : "r"(la), "r"((uint32_t)(lane - CLU)));
            asm volatile("ld.shared::cluster.b32 %0, [%1];" : "=f"(kz) : "r"(ra));
        }
        kz = __shfl_down_sync(0xffffffffu, kz, CLU);
#pragma unroll
        for (int o = 4; o; o >>= 1) {
            ull  ok = __shfl_xor_sync(0xffffffffu, kk,  o);
            ull  oxy= __shfl_xor_sync(0xffffffffu, kxy, o);
            float oz= __shfl_xor_sync(0xffffffffu, kz,  o);
            if (ok > kk) { kk = ok; kxy = oxy; kz = oz; }
        }
        kk  = __shfl_sync(0xffffffffu, kk,  0);
        kxy = __shfl_sync(0xffffffffu, kxy, 0);
        kz  = __shfl_sync(0xffffffffu, kz,  0);
        if (rank == 0 && t == 0) {
            fidx[(size_t)b*2048 + j] = 16383 - (int)(kk & 0x3FFFu);
            float wx, wy; upkxy(kxy, wx, wy);
            float* o = nxyz + ((size_t)b*2048 + j)*3;
            o[0] = wx; o[1] = wy; o[2] = kz;
        }
        upkxy(kxy, cx, cy); cz = kz;
    }
}

// ============ FPS stages 2-4 device body ============
template<int BLK, int P>
__device__ __forceinline__ void fps_reg_dev(const float* __restrict__ xyz, int npoint,
                                            int* __restrict__ fidx, float* __restrict__ nxyz,
                                            int b, float* sm)
{
    const int N = BLK * P;
    float* sx = sm; float* sy = sm + N; float* sz = sm + 2*N;
    __shared__ float rv[32];
    __shared__ int   ri[32];
    __shared__ float s_cxyz[3];

    const int t = threadIdx.x;
    const float* base = xyz + (size_t)b * N * 3;
    float px[P], py[P], pz[P], dst[P];
#pragma unroll
    for (int k = 0; k < P; k++) {
        int i = t + k*BLK;
        px[k] = base[i*3+0]; py[k] = base[i*3+1]; pz[k] = base[i*3+2];
        sx[i] = px[k]; sy[i] = py[k]; sz[i] = pz[k];
        dst[k] = 1e10f;
    }
    if (t == 0) {
        s_cxyz[0] = px[0]; s_cxyz[1] = py[0]; s_cxyz[2] = pz[0];
        fidx[(size_t)b*npoint] = 0;
        float* o = nxyz + (size_t)b*npoint*3;
        o[0] = px[0]; o[1] = py[0]; o[2] = pz[0];
    }
    __syncthreads();

    for (int j = 1; j < npoint; j++) {
        const float cx = s_cxyz[0], cy = s_cxyz[1], cz = s_cxyz[2];
        float best = -1.0f; int bi = 0x7fffffff;
#pragma unroll
        for (int k = 0; k < P; k++) {
            float dx = px[k]-cx, dy = py[k]-cy, dz = pz[k]-cz;
            float nd = fminf(dst[k], dx*dx + dy*dy + dz*dz);
            dst[k] = nd;
            if (nd > best) { best = nd; bi = t + k*BLK; }
        }
#pragma unroll
        for (int off = 16; off; off >>= 1) {
            float ov = __shfl_down_sync(0xffffffffu, best, off);
            int   oi = __shfl_down_sync(0xffffffffu, bi,   off);
            if (ov > best || (ov == best && oi < bi)) { best = ov; bi = oi; }
        }
        int w = t >> 5;
        if ((t & 31) == 0) { rv[w] = best; ri[w] = bi; }
        __syncthreads();
        if (t < 32) {
            const int nw = BLK / 32;
            float v  = (t < nw) ? rv[t] : -1.0f;
            int   i2 = (t < nw) ? ri[t] : 0x7fffffff;
#pragma unroll
            for (int off = 16; off; off >>= 1) {
                float ov = __shfl_down_sync(0xffffffffu, v,  off);
                int   oi = __shfl_down_sync(0xffffffffu, i2, off);
                if (ov > v || (ov == v && oi < i2)) { v = ov; i2 = oi; }
            }
            if (t == 0) {
                fidx[(size_t)b*npoint + j] = i2;
                float wx = sx[i2], wy = sy[i2], wz = sz[i2];
                s_cxyz[0] = wx; s_cxyz[1] = wy; s_cxyz[2] = wz;
                float* o = nxyz + ((size_t)b*npoint + j)*3;
                o[0] = wx; o[1] = wy; o[2] = wz;
            }
        }
        __syncthreads();
    }
}

__global__ void pack4_kernel(const float* __restrict__ xyz, float4* __restrict__ pk, int total)
{
    int i = blockIdx.x*blockDim.x + threadIdx.x;
    if (i >= total) return;
    float x = xyz[i*3+0], y = xyz[i*3+1], z = xyz[i*3+2];
    pk[i] = make_float4(x, y, z, (x*x + y*y) + z*z);
}

// ============ ball query device body (SoA, warp-per-center) ============
__device__ __forceinline__ void bq_dev(const float* __restrict__ xyz, const float* __restrict__ nxyz,
                                       int* __restrict__ nidx, int S, int N, int nsample,
                                       float r2, int gw)
{
    int lane = threadIdx.x & 31;
    int b = gw / S;
    const float* xb = xyz + (size_t)b * N * 3;
    float nx = nxyz[gw*3+0], ny = nxyz[gw*3+1], nz = nxyz[gw*3+2];
    float sn = (nx*nx + ny*ny) + nz*nz;
    int* out = nidx + (size_t)gw * nsample;

    int cnt = 0, first = -1;
    for (int base = 0; base < N; base += 32) {
        int j = base + lane;
        float x = xb[j*3+0], y = xb[j*3+1], z = xb[j*3+2];
        float sxx = (x*x + y*y) + z*z;
        float dot = (nx*x + ny*y) + nz*z;
        bool in = ((sn + sxx) - 2.0f*dot) < r2;
        unsigned m = __ballot_sync(0xffffffffu, in);
        if (in) {
            int pos = cnt + __popc(m & ((1u << lane) - 1u));
            if (pos < nsample) out[pos] = j;
        }
        if (first < 0 && m) first = base + __ffs(m) - 1;
        cnt += __popc(m);
        if (cnt >= nsample) break;
    }
    for (int p = cnt + lane; p < nsample; p += 32) out[p] = first;
}

// ============ stage-1 ball query body: SMEM-tiled cloud ============
#define BQ_CH 2048
__device__ __forceinline__ void bq1_dev(const float4* __restrict__ pk, const float* __restrict__ nxyz,
                                        int* __restrict__ nidx, int blk, float4* sp)
{
    const int t = threadIdx.x, w = t >> 5, lane = t & 31;
    const int gw = blk * 8 + w;
    const int b = gw >> 11;
    const float4* xb = pk + (size_t)b * 16384;
    const float nx = nxyz[gw*3+0], ny = nxyz[gw*3+1], nz = nxyz[gw*3+2];
    const float sn = (nx*nx + ny*ny) + nz*nz;
    int* out = nidx + (size_t)gw * 64;

    int cnt = 0, first = -1;
    bool done = false;
    for (int base = 0; base < 16384; base += BQ_CH) {
        __syncthreads();
#pragma unroll
        for (int q = 0; q < BQ_CH/256; q++)
            sp[t + q*256] = xb[base + t + q*256];
        __syncthreads();
        if (done) continue;
        for (int inner = 0; inner < BQ_CH; inner += 32) {
            float4 p = sp[inner + lane];
            float dot = (nx*p.x + ny*p.y) + nz*p.z;
            bool in = ((sn + p.w) - 2.0f*dot) < 0.04f;
            unsigned m = __ballot_sync(0xffffffffu, in);
            if (in) {
                int pos = cnt + __popc(m & ((1u << lane) - 1u));
                if (pos < 64) out[pos] = base + inner + lane;
            }
            if (first < 0 && m) first = base + inner + __ffs(m) - 1;
            cnt += __popc(m);
            if (cnt >= 64) { done = true; break; }
        }
    }
    for (int p = cnt + lane; p < 64; p += 32) out[p] = first;
}

// ============ sa1 device body (R12-proven) ============
#define SA1_SMEM 12928
__device__ __forceinline__ void sa1_dev(const float* __restrict__ xyz, const float* __restrict__ nxyz,
                const int* __restrict__ nidx,
                const float* __restrict__ w0, const float* __restrict__ b0,
                const float* __restrict__ w1, const float* __restrict__ b1,
                const float* __restrict__ w2, const float* __restrict__ b2,
                float* __restrict__ feats, float radius, int ctr, float* sm)
{
    float* sW0 = sm;
    float* sB0 = sm + 192;
    float* sW1 = sm + 256;
    float* sB1 = sm + 4352;
    float* sB2 = sm + 4416;
    float* sR  = sm + 4544;
    float* sH0 = sm + 4736;
    float* sH1 = sm + 8832;

    const int t = threadIdx.x;
    const int b = ctr >> 11;

    for (int i = t; i < 192;  i += 128) sW0[i] = w0[i];
    if (t < 64) { sB0[t] = b0[t]; sB1[t] = b1[t]; }
    for (int i = t; i < 4096; i += 128) sW1[i] = w1[i];
    sB2[t] = b2[t];
    if (t < 64) {
        int id = nidx[(size_t)ctr*64 + t];
        const float* p = xyz + ((size_t)(b << 14) + id)*3;
        sR[t*3+0] = (p[0] - nxyz[ctr*3+0]) / radius;
        sR[t*3+1] = (p[1] - nxyz[ctr*3+1]) / radius;
        sR[t*3+2] = (p[2] - nxyz[ctr*3+2]) / radius;
    }
    __syncthreads();

    {
        int n = t & 63, half = t >> 6;
        float rx = sR[n*3+0], ry = sR[n*3+1], rz = sR[n*3+2];
#pragma unroll 8
        for (int cc = 0; cc < 32; cc++) {
            int c = half*32 + cc;
            float v = sB0[c] + rx*sW0[c] + ry*sW0[64+c] + rz*sW0[128+c];
            sH0[c*64 + n] = fmaxf(v, 0.0f);
        }
    }
    __syncthreads();

    const int ng = t & 15, cg = t >> 4;
    float acc[32];

#pragma unroll
    for (int i = 0; i < 4; i++)
#pragma unroll
        for (int jj = 0; jj < 8; jj++) acc[i*8+jj] = sB1[8*cg + jj];
#pragma unroll 8
    for (int k = 0; k < 64; k++) {
        float4 a = *(const float4*)&sH0[k*64 + 4*ng];
        float4 u = *(const float4*)&sW1[k*64 + 8*cg];
        float4 v = *(const float4*)&sW1[k*64 + 8*cg + 4];
        float av[4] = {a.x, a.y, a.z, a.w};
        float bv[8] = {u.x, u.y, u.z, u.w, v.x, v.y, v.z, v.w};
#pragma unroll
        for (int i = 0; i < 4; i++)
#pragma unroll
            for (int jj = 0; jj < 8; jj++) acc[i*8+jj] += av[i]*bv[jj];
    }
#pragma unroll
    for (int jj = 0; jj < 8; jj++) {
        float4 o;
        o.x = fmaxf(acc[0*8+jj], 0.0f);
        o.y = fmaxf(acc[1*8+jj], 0.0f);
        o.z = fmaxf(acc[2*8+jj], 0.0f);
        o.w = fmaxf(acc[3*8+jj], 0.0f);
        *(float4*)&sH1[(8*cg+jj)*64 + 4*ng] = o;
    }
    __syncthreads();

#pragma unroll 1
    for (int pass = 0; pass < 2; pass++) {
        int c0 = pass*64 + 8*cg;
#pragma unroll
        for (int i = 0; i < 4; i++)
#pragma unroll
            for (int jj = 0; jj < 8; jj++) acc[i*8+jj] = sB2[c0 + jj];
#pragma unroll 4
        for (int k = 0; k < 64; k++) {
            float4 a = *(const float4*)&sH1[k*64 + 4*ng];
            float4 u = *(const float4*)&w2[k*128 + c0];
            float4 v = *(const float4*)&w2[k*128 + c0 + 4];
            float av[4] = {a.x, a.y, a.z, a.w};
            float bv[8] = {u.x, u.y, u.z, u.w, v.x, v.y, v.z, v.w};
#pragma unroll
            for (int i = 0; i < 4; i++)
#pragma unroll
                for (int jj = 0; jj < 8; jj++) acc[i*8+jj] += av[i]*bv[jj];
        }
#pragma unroll
        for (int jj = 0; jj < 8; jj++) {
            float m = fmaxf(fmaxf(fmaxf(acc[0*8+jj], 0.0f), fmaxf(acc[1*8+jj], 0.0f)),
                            fmaxf(fmaxf(acc[2*8+jj], 0.0f), fmaxf(acc[3*8+jj], 0.0f)));
#pragma unroll
            for (int off = 8; off; off >>= 1)
                m = fmaxf(m, __shfl_xor_sync(0xffffffffu, m, off));
            if (ng == 0) feats[(size_t)ctr*128 + c0 + jj] = m;
        }
    }
}

// ============ GEMM device bodies: ping-pong SMEM double-buffer (ONE sync per K-step) ============
__device__ __forceinline__ void gemm128_dev(const float* __restrict__ A, const float* __restrict__ W,
             const float* __restrict__ bias, float* __restrict__ Y,
             int M, int N, int K, int bxv, int byv)
{
    __shared__ __align__(16) float As[2][8][128];
    __shared__ __align__(16) float Bs[2][8][128];
    const int bm = byv * 128;
    const int bn = bxv * 128;
    const int t  = threadIdx.x;
    const int ty = t >> 4, tx = t & 15;
    float acc[8][8];
#pragma unroll
    for (int i = 0; i < 8; i++)
#pragma unroll
        for (int j = 0; j < 8; j++) acc[i][j] = 0.0f;

    const int abr = t >> 5;
    const int abc = (t & 31) * 4;
    const int ar0 = (t*4) >> 3;
    const int ac0 = (t*4) & 7;

    float ra[4]; float4 rb;
#pragma unroll
    for (int q = 0; q < 4; q++) {
        int kk = ac0 + q;
        ra[q] = (kk < K) ? A[(size_t)(bm + ar0)*K + kk] : 0.0f;
    }
    rb = (abr < K) ? *(const float4*)&W[(size_t)abr*N + bn + abc]
                   : make_float4(0.f,0.f,0.f,0.f);
#pragma unroll
    for (int q = 0; q < 4; q++) As[0][ac0 + q][ar0] = ra[q];
    *(float4*)&Bs[0][abr][abc] = rb;
    __syncthreads();

    for (int k0 = 0; k0 < K; k0 += 8) {
        const int cur = (k0 >> 3) & 1;
        if (k0 + 8 < K) {
#pragma unroll
            for (int q = 0; q < 4; q++) {
                int kk = k0 + 8 + ac0 + q;
                ra[q] = (kk < K) ? A[(size_t)(bm + ar0)*K + kk] : 0.0f;
            }
            int kk = k0 + 8 + abr;
            rb = (kk < K) ? *(const float4*)&W[(size_t)kk*N + bn + abc]
                          : make_float4(0.f,0.f,0.f,0.f);
        }
#pragma unroll
        for (int kk = 0; kk < 8; kk++) {
            float4 a0 = *(const float4*)&As[cur][kk][ty*8];
            float4 a1 = *(const float4*)&As[cur][kk][ty*8 + 4];
            float4 b0 = *(const float4*)&Bs[cur][kk][tx*8];
            float4 b1 = *(const float4*)&Bs[cur][kk][tx*8 + 4];
            float av[8] = {a0.x, a0.y, a0.z, a0.w, a1.x, a1.y, a1.z, a1.w};
            float bv[8] = {b0.x, b0.y, b0.z, b0.w, b1.x, b1.y, b1.z, b1.w};
#pragma unroll
            for (int i = 0; i < 8; i++)
#pragma unroll
                for (int j = 0; j < 8; j++) acc[i][j] += av[i]*bv[j];
        }
        if (k0 + 8 < K) {
#pragma unroll
            for (int q = 0; q < 4; q++) As[cur^1][ac0 + q][ar0] = ra[q];
            *(float4*)&Bs[cur^1][abr][abc] = rb;
            __syncthreads();
        }
    }
    float4 bb0 = *(const float4*)&bias[bn + tx*8];
    float4 bb1 = *(const float4*)&bias[bn + tx*8 + 4];
    float bv[8] = {bb0.x, bb0.y, bb0.z, bb0.w, bb1.x, bb1.y, bb1.z, bb1.w};
#pragma unroll
    for (int i = 0; i < 8; i++) {
        size_t row = (size_t)(bm + ty*8 + i);
        float4 o0, o1;
        o0.x = fmaxf(acc[i][0]+bv[0], 0.f); o0.y = fmaxf(acc[i][1]+bv[1], 0.f);
        o0.z = fmaxf(acc[i][2]+bv[2], 0.f); o0.w = fmaxf(acc[i][3]+bv[3], 0.f);
        o1.x = fmaxf(acc[i][4]+bv[4], 0.f); o1.y = fmaxf(acc[i][5]+bv[5], 0.f);
        o1.z = fmaxf(acc[i][6]+bv[6], 0.f); o1.w = fmaxf(acc[i][7]+bv[7], 0.f);
        *(float4*)&Y[row*N + bn + tx*8]     = o0;
        *(float4*)&Y[row*N + bn + tx*8 + 4] = o1;
    }
}

__device__ __forceinline__ void gemm128g_dev(const float* __restrict__ xyz, const float* __restrict__ nxyz,
              const int* __restrict__ nidx, const float* __restrict__ feats,
              const float* __restrict__ W, const float* __restrict__ bias,
              float* __restrict__ Y, int M, int N, int K,
              int ns, int npts, int C, float radius, int rows_pb, int bxv, int byv)
{
    __shared__ __align__(16) float Asg[2][8][128];
    __shared__ __align__(16) float Bsg[2][8][128];
    const int bm = byv * 128;
    const int bn = bxv * 128;
    const int t  = threadIdx.x;
    const int ty = t >> 4, tx = t & 15;
    float acc[8][8];
#pragma unroll
    for (int i = 0; i < 8; i++)
#pragma unroll
        for (int j = 0; j < 8; j++) acc[i][j] = 0.0f;

    const int ar  = (t*4) >> 3;
    const int ac0 = (t*4) & 7;
    const int row = bm + ar;
    const int ci  = row / ns;
    const int b   = row / rows_pb;
    const int id  = nidx[row];
    const float* pt = xyz + ((size_t)b*npts + id)*3;
    const float* fr = feats + ((size_t)b*npts + id)*C;
    float rel[3];
#pragma unroll
    for (int cc = 0; cc < 3; cc++) rel[cc] = (pt[cc] - nxyz[ci*3+cc]) / radius;

    const int abr = t >> 5;
    const int abc = (t & 31) * 4;

    float ra[4]; float4 rb;
#pragma unroll
    for (int q = 0; q < 4; q++) {
        int kk = ac0 + q;
        ra[q] = (kk < 3) ? rel[kk] : ((kk < K) ? fr[kk-3] : 0.0f);
    }
    rb = (abr < K) ? *(const float4*)&W[(size_t)abr*N + bn + abc]
                   : make_float4(0.f,0.f,0.f,0.f);
#pragma unroll
    for (int q = 0; q < 4; q++) Asg[0][ac0 + q][ar] = ra[q];
    *(float4*)&Bsg[0][abr][abc] = rb;
    __syncthreads();

    for (int k0 = 0; k0 < K; k0 += 8) {
        const int cur = (k0 >> 3) & 1;
        if (k0 + 8 < K) {
#pragma unroll
            for (int q = 0; q < 4; q++) {
                int kk = k0 + 8 + ac0 + q;
                ra[q] = (kk < 3) ? rel[kk] : ((kk < K) ? fr[kk-3] : 0.0f);
            }
            int kk = k0 + 8 + abr;
            rb = (kk < K) ? *(const float4*)&W[(size_t)kk*N + bn + abc]
                          : make_float4(0.f,0.f,0.f,0.f);
        }
#pragma unroll
        for (int kk = 0; kk < 8; kk++) {
            float4 a0 = *(const float4*)&Asg[cur][kk][ty*8];
            float4 a1 = *(const float4*)&Asg[cur][kk][ty*8 + 4];
            float4 b0 = *(const float4*)&Bsg[cur][kk][tx*8];
            float4 b1 = *(const float4*)&Bsg[cur][kk][tx*8 + 4];
            float av[8] = {a0.x, a0.y, a0.z, a0.w, a1.x, a1.y, a1.z, a1.w};
            float bv[8] = {b0.x, b0.y, b0.z, b0.w, b1.x, b1.y, b1.z, b1.w};
#pragma unroll
            for (int i = 0; i < 8; i++)
#pragma unroll
                for (int j = 0; j < 8; j++) acc[i][j] += av[i]*bv[j];
        }
        if (k0 + 8 < K) {
#pragma unroll
            for (int q = 0; q < 4; q++) Asg[cur^1][ac0 + q][ar] = ra[q];
            *(float4*)&Bsg[cur^1][abr][abc] = rb;
            __syncthreads();
        }
    }
    float4 bb0 = *(const float4*)&bias[bn + tx*8];
    float4 bb1 = *(const float4*)&bias[bn + tx*8 + 4];
    float bv[8] = {bb0.x, bb0.y, bb0.z, bb0.w, bb1.x, bb1.y, bb1.z, bb1.w};
#pragma unroll
    for (int i = 0; i < 8; i++) {
        size_t orow = (size_t)(bm + ty*8 + i);
        float4 o0, o1;
        o0.x = fmaxf(acc[i][0]+bv[0], 0.f); o0.y = fmaxf(acc[i][1]+bv[1], 0.f);
        o0.z = fmaxf(acc[i][2]+bv[2], 0.f); o0.w = fmaxf(acc[i][3]+bv[3], 0.f);
        o1.x = fmaxf(acc[i][4]+bv[4], 0.f); o1.y = fmaxf(acc[i][5]+bv[5], 0.f);
        o1.z = fmaxf(acc[i][6]+bv[6], 0.f); o1.w = fmaxf(acc[i][7]+bv[7], 0.f);
        *(float4*)&Y[orow*N + bn + tx*8]     = o0;
        *(float4*)&Y[orow*N + bn + tx*8 + 4] = o1;
    }
}

__global__ __launch_bounds__(256)
void gemm128(const float* A, const float* W, const float* bias, float* Y, int M, int N, int K)
{ gemm128_dev(A, W, bias, Y, M, N, K, blockIdx.x, blockIdx.y); }

__global__ __launch_bounds__(256)
void gemm128g(const float* xyz, const float* nxyz, const int* nidx, const float* feats,
              const float* W, const float* bias, float* Y, int M, int N, int K,
              int ns, int npts, int C, float radius, int rows_pb)
{ gemm128g_dev(xyz, nxyz, nidx, feats, W, bias, Y, M, N, K, ns, npts, C, radius, rows_pb, blockIdx.x, blockIdx.y); }

// ============ GEMM + bias + relu + fused maxpool (ping-pong) ============
template<int NS>
__global__ __launch_bounds__(256)
void gemm128_mp(const float* __restrict__ A, const float* __restrict__ W,
                const float* __restrict__ bias, float* __restrict__ out,
                int M, int N, int K)
{
    __shared__ __align__(16) float As[2][8][128];
    __shared__ __align__(16) float Bs[2][8][128];
    __shared__ float red[16][136];
    const int bm = blockIdx.y * 128;
    const int bn = blockIdx.x * 128;
    const int t  = threadIdx.x;
    const int ty = t >> 4, tx = t & 15;
    float acc[8][8];
#pragma unroll
    for (int i = 0; i < 8; i++)
#pragma unroll
        for (int j = 0; j < 8; j++) acc[i][j] = 0.0f;

    const int abr = t >> 5;
    const int abc = (t & 31) * 4;
    const int ar0 = (t*4) >> 3;
    const int ac0 = (t*4) & 7;

    float ra[4]; float4 rb;
#pragma unroll
    for (int q = 0; q < 4; q++) {
        int kk = ac0 + q;
        ra[q] = (kk < K) ? A[(size_t)(bm + ar0)*K + kk] : 0.0f;
    }
    rb = (abr < K) ? *(const float4*)&W[(size_t)abr*N + bn + abc]
                   : make_float4(0.f,0.f,0.f,0.f);
#pragma unroll
    for (int q = 0; q < 4; q++) As[0][ac0 + q][ar0] = ra[q];
    *(float4*)&Bs[0][abr][abc] = rb;
    __syncthreads();

    for (int k0 = 0; k0 < K; k0 += 8) {
        const int cur = (k0 >> 3) & 1;
        if (k0 + 8 < K) {
#pragma unroll
            for (int q = 0; q < 4; q++) {
                int kk = k0 + 8 + ac0 + q;
                ra[q] = (kk < K) ? A[(size_t)(bm + ar0)*K + kk] : 0.0f;
            }
            int kk = k0 + 8 + abr;
            rb = (kk < K) ? *(const float4*)&W[(size_t)kk*N + bn + abc]
                          : make_float4(0.f,0.f,0.f,0.f);
        }
#pragma unroll
        for (int kk = 0; kk < 8; kk++) {
            float4 a0 = *(const float4*)&As[cur][kk][ty*8];
            float4 a1 = *(const float4*)&As[cur][kk][ty*8 + 4];
            float4 b0 = *(const float4*)&Bs[cur][kk][tx*8];
            float4 b1 = *(const float4*)&Bs[cur][kk][tx*8 + 4];
            float av[8] = {a0.x, a0.y, a0.z, a0.w, a1.x, a1.y, a1.z, a1.w};
            float bv[8] = {b0.x, b0.y, b0.z, b0.w, b1.x, b1.y, b1.z, b1.w};
#pragma unroll
            for (int i = 0; i < 8; i++)
#pragma unroll
                for (int j = 0; j < 8; j++) acc[i][j] += av[i]*bv[j];
        }
        if (k0 + 8 < K) {
#pragma unroll
            for (int q = 0; q < 4; q++) As[cur^1][ac0 + q][ar0] = ra[q];
            *(float4*)&Bs[cur^1][abr][abc] = rb;
            __syncthreads();
        }
    }
    float4 bb0 = *(const float4*)&bias[bn + tx*8];
    float4 bb1 = *(const float4*)&bias[bn + tx*8 + 4];
    float bv[8] = {bb0.x, bb0.y, bb0.z, bb0.w, bb1.x, bb1.y, bb1.z, bb1.w};
#pragma unroll
    for (int j = 0; j < 8; j++) {
        float m = fmaxf(acc[0][j] + bv[j], 0.0f);
#pragma unroll
        for (int i = 1; i < 8; i++) m = fmaxf(m, fmaxf(acc[i][j] + bv[j], 0.0f));
        red[ty][tx*8 + j] = m;
    }
    __syncthreads();
    const int g = NS / 8;
    if ((ty % g) == 0) {
        int center = (bm + ty*8) / NS;
#pragma unroll
        for (int j = 0; j < 8; j++) {
            float m = red[ty][tx*8 + j];
#pragma unroll
            for (int r = 1; r < g; r++) m = fmaxf(m, red[ty + r][tx*8 + j]);
            out[(size_t)center*N + bn + tx*8 + j] = m;
        }
    }
}

// ================== fat combo kernels (R12-proven) ==================
// L3 (256 thr, dyn 32KB): [0,1024) bq1 | [1024,1028) fps2
__global__ __launch_bounds__(256)
void combo_L3(const float4* pk4, const float* nx1, int* nidx1,
              int* fidx, float* nx2)
{
    extern __shared__ float smf[];
    int bid = blockIdx.x;
    if (bid < 1024) {
        bq1_dev(pk4, nx1, nidx1, bid, (float4*)smf);
    } else {
        fps_reg_dev<256,8>(nx1, 1024, fidx, nx2, bid - 1024, smf);
    }
}

// L4 (128 thr, dyn 51712B): [0,8192) sa1 | [8192,9216) bq2 (4 warps/blk) | [9216,9220) fps3
__global__ __launch_bounds__(128)
void combo_L4(const float* pc, const float* nx1, const int* nidx1,
              const float* w0, const float* b0, const float* w1, const float* b1,
              const float* w2, const float* b2, float* f1,
              const float* nx2, int* nidx2, int* fidx, float* nx3)
{
    extern __shared__ float smf[];
    int bid = blockIdx.x;
    if (bid < 8192) {
        sa1_dev(pc, nx1, nidx1, w0,b0,w1,b1,w2,b2, f1, 0.2f, bid, smf);
    } else if (bid < 9216) {
        int gw = (bid - 8192)*4 + (threadIdx.x >> 5);
        bq_dev(nx1, nx2, nidx2, 1024, 2048, 32, 0.16f, gw);
    } else {
        fps_reg_dev<128,8>(nx2, 512, fidx, nx3, bid - 9216, smf);
    }
}

// L5 (256 thr): [0,1024) gemm_g2 | [1024,1280) bq3 (8 warps/blk) | [1280,1284) fps4
__global__ __launch_bounds__(256)
void combo_L5(const float* nx1, const float* nx2, const int* nidx2, const float* f1,
              const float* w20, const float* b20, float* YA,
              const float* nx3, int* nidx3, int* fidx, float* nx4)
{
    extern __shared__ float smf[];
    int bid = blockIdx.x;
    if (bid < 1024) {
        gemm128g_dev(nx1, nx2, nidx2, f1, w20, b20, YA, 131072, 128, 131, 32, 2048, 128, 0.4f, 32768, 0, bid);
    } else if (bid < 1280) {
        int gw = (bid - 1024)*8 + (threadIdx.x >> 5);
        bq_dev(nx2, nx3, nidx3, 512, 1024, 16, 0.36f, gw);
    } else {
        fps_reg_dev<256,2>(nx3, 256, fidx, nx4, bid - 1280, smf);
    }
}

// L6 (256 thr): [0,1024) gemm mid-2 | [1024,1152) bq4 (8 warps/blk)
__global__ __launch_bounds__(256)
void combo_L6(const float* YA, const float* w21, const float* b21, float* YB,
              const float* nx3, const float* nx4, int* nidx4)
{
    int bid = blockIdx.x;
    if (bid < 1024) {
        gemm128_dev(YA, w21, b21, YB, 131072, 128, 128, 0, bid);
    } else {
        int gw = (bid - 1024)*8 + (threadIdx.x >> 5);
        bq_dev(nx3, nx4, nidx4, 256, 512, 8, 1.44f, gw);
    }
}

static inline int cdiv(int a, int b) { return (a + b - 1) / b; }

extern "C" void kernel_launch(void* const* d_in, const int* in_sizes, int n_in,
                              void* d_out, int out_size)
{
    (void)in_sizes; (void)n_in; (void)out_size;
    const float* pc  = (const float*)d_in[0];
    const float* w10 = (const float*)d_in[1],  *b10 = (const float*)d_in[2];
    const float* w11 = (const float*)d_in[3],  *b11 = (const float*)d_in[4];
    const float* w12 = (const float*)d_in[5],  *b12 = (const float*)d_in[6];
    const float* w20 = (const float*)d_in[7],  *b20 = (const float*)d_in[8];
    const float* w21 = (const float*)d_in[9],  *b21 = (const float*)d_in[10];
    const float* w22 = (const float*)d_in[11], *b22 = (const float*)d_in[12];
    const float* w30 = (const float*)d_in[13], *b30 = (const float*)d_in[14];
    const float* w31 = (const float*)d_in[15], *b31 = (const float*)d_in[16];
    const float* w32 = (const float*)d_in[17], *b32 = (const float*)d_in[18];
    const float* w40 = (const float*)d_in[19], *b40 = (const float*)d_in[20];
    const float* w41 = (const float*)d_in[21], *b41 = (const float*)d_in[22];
    const float* w42 = (const float*)d_in[23], *b42 = (const float*)d_in[24];

    float *nx1, *nx2, *nx3, *f1, *f2, *f3, *YA, *YB;
    float4 *pk4;
    int *fidx, *nidx;
    cudaGetSymbolAddress((void**)&nx1,  g_nx1);
    cudaGetSymbolAddress((void**)&nx2,  g_nx2);
    cudaGetSymbolAddress((void**)&nx3,  g_nx3);
    cudaGetSymbolAddress((void**)&f1,   g_f1);
    cudaGetSymbolAddress((void**)&f2,   g_f2);
    cudaGetSymbolAddress((void**)&f3,   g_f3);
    cudaGetSymbolAddress((void**)&YA,   g_YA);
    cudaGetSymbolAddress((void**)&YB,   g_YB);
    cudaGetSymbolAddress((void**)&fidx, g_fidx);
    cudaGetSymbolAddress((void**)&nidx, g_nidx);
    cudaGetSymbolAddress((void**)&pk4,  g_pk4);
    int* nidx1 = nidx;
    int* nidx2 = nidx + 524288;
    int* nidx3 = nidx + 655360;
    int* nidx4 = nidx + 688128;

    cudaFuncSetAttribute((const void*)combo_L4,
                         cudaFuncAttributeMaxDynamicSharedMemorySize, SA1_SMEM*4);

    float* out = (float*)d_out;
    float* nx4 = out;          // [4,256,3]
    float* f4  = out + 3072;   // [4,256,512]

    pack4_kernel<<<cdiv(NB*16384,256),256>>>(pc, pk4, NB*16384);
    fps1_cluster<<<NB*CLU, 256>>>(pc, fidx, nx1);
    combo_L3<<<1028, 256, 32768>>>(pk4, nx1, nidx1, fidx, nx2);
    combo_L4<<<9220, 128, SA1_SMEM*4>>>(pc, nx1, nidx1, w10,b10,w11,b11,w12,b12, f1,
                                        nx2, nidx2, fidx, nx3);
    combo_L5<<<1284, 256, 6144>>>(nx1, nx2, nidx2, f1, w20, b20, YA, nx3, nidx3, fidx, nx4);
    combo_L6<<<1152, 256>>>(YA, w21, b21, YB, nx3, nx4, nidx4);
    gemm128_mp<32><<<dim3(2, 1024), 256>>>(YB, w22, b22, f2, 131072, 256, 128);

    // Stage 3 MLP
    gemm128g<<<dim3(2, 256), 256>>>(nx2, nx3, nidx3, f2, w30, b30, YA, 32768, 256, 259, 16, 1024, 256, 0.6f, 8192);
    gemm128<<<dim3(2, 256), 256>>>(YA, w31, b31, YB, 32768, 256, 256);
    gemm128_mp<16><<<dim3(4, 256), 256>>>(YB, w32, b32, f3, 32768, 512, 256);

    // Stage 4 MLP
    gemm128g<<<dim3(4, 64), 256>>>(nx3, nx4, nidx4, f3, w40, b40, YA, 8192, 512, 515, 8, 512, 512, 1.2f, 2048);
    gemm128<<<dim3(4, 64), 256>>>(YA, w41, b41, YB, 8192, 512, 512);
    gemm128_mp<8><<<dim3(4, 64), 256>>>(YB, w42, b42, f4, 8192, 512, 512);
}

// round 16
// speedup vs baseline: 1.5655x; 1.0317x over previous
#include <cuda_runtime.h>
#include <cstdint>

#define NB 4
typedef unsigned long long ull;

// ---------------- static device scratch ----------------
__device__ float g_nx1[NB*2048*3];
__device__ float g_nx2[NB*1024*3];
__device__ float g_nx3[NB*512*3];
__device__ float g_f1[NB*2048*128];
__device__ float g_f2[NB*1024*256];
__device__ float g_f3[NB*512*512];
__device__ int   g_fidx[NB*2048];
__device__ int   g_nidx[720896];     // nidx1@0 | nidx2@524288 | nidx3@655360 | nidx4@688128
__device__ float g_YA[33554432];
__device__ float g_YB[16777216];
__device__ float4 g_pk4[NB*16384];

__device__ __forceinline__ uint32_t smem_u32(const void* p) {
    uint32_t a;
    asm("{ .reg .u64 t; cvta.to.shared.u64 t, %1; cvt.u32.u64 %0, t; }" : "=r"(a) : "l"(p));
    return a;
}
__device__ __forceinline__ ull pkxy(float x, float y) {
    ull r; asm("mov.b64 %0, {%1, %2};" : "=l"(r) : "f"(x), "f"(y)); return r;
}
__device__ __forceinline__ void upkxy(ull v, float& x, float& y) {
    asm("mov.b64 {%0, %1}, %2;" : "=f"(x), "=f"(y) : "l"(v));
}

// ================== FPS stage 1: 8-CTA cluster, 256 thr, all-warp pull (proven) ==================
#define CLU 8
__global__ __launch_bounds__(256) __cluster_dims__(CLU, 1, 1)
void fps1_cluster(const float* __restrict__ xyz, int* __restrict__ fidx,
                  float* __restrict__ nxyz)
{
    __shared__ ull   s_wk[8];
    __shared__ ull   s_wxy[8];
    __shared__ float s_wz[8];
    __shared__ __align__(16) ull s_ex[2][2];
    __shared__ float s_exz[2];

    const int t = threadIdx.x, lane = t & 31, w = t >> 5;
    uint32_t rank; asm("mov.u32 %0, %%cluster_ctarank;" : "=r"(rank));
    const int b = blockIdx.x / CLU;
    const float* base = xyz + (size_t)b*16384*3;

    float px[8], py[8], pz[8], dd[8];
#pragma unroll
    for (int k = 0; k < 8; k++) {
        int i = (int)rank*2048 + k*256 + t;
        px[k] = base[i*3]; py[k] = base[i*3+1]; pz[k] = base[i*3+2];
        dd[k] = 1e10f;
    }
    float cx = base[0], cy = base[1], cz = base[2];
    if (rank == 0 && t == 0) {
        fidx[(size_t)b*2048] = 0;
        float* o = nxyz + (size_t)b*2048*3;
        o[0] = cx; o[1] = cy; o[2] = cz;
    }

    for (int j = 1; j < 2048; j++) {
        const int p = j & 1;
        float bd = -1.0f, bx = 0, by = 0, bz = 0; int bidx = 0;
#pragma unroll
        for (int k = 0; k < 8; k++) {
            float dx = px[k]-cx, dy = py[k]-cy, dz = pz[k]-cz;
            float nd = fminf(dd[k], dx*dx + dy*dy + dz*dz);
            dd[k] = nd;
            if (nd > bd) { bd = nd; bidx = (int)rank*2048 + k*256 + t; bx = px[k]; by = py[k]; bz = pz[k]; }
        }
        ull key = ((ull)__float_as_uint(bd) << 32) | (ull)(16383 - bidx);
        ull xy  = pkxy(bx, by);
#pragma unroll
        for (int o = 16; o; o >>= 1) {
            ull  ok = __shfl_xor_sync(0xffffffffu, key, o);
            ull  oxy= __shfl_xor_sync(0xffffffffu, xy,  o);
            float oz= __shfl_xor_sync(0xffffffffu, bz,  o);
            if (ok > key) { key = ok; xy = oxy; bz = oz; }
        }
        if (lane == 0) { s_wk[w] = key; s_wxy[w] = xy; s_wz[w] = bz; }
        __syncthreads();
        if (w == 0) {
            key = (lane < 8) ? s_wk[lane] : 0;
            xy  = (lane < 8) ? s_wxy[lane] : 0;
            bz  = (lane < 8) ? s_wz[lane] : 0.0f;
#pragma unroll
            for (int o = 4; o; o >>= 1) {
                ull  ok = __shfl_xor_sync(0xffffffffu, key, o);
                ull  oxy= __shfl_xor_sync(0xffffffffu, xy,  o);
                float oz= __shfl_xor_sync(0xffffffffu, bz,  o);
                if (ok > key) { key = ok; xy = oxy; bz = oz; }
            }
            if (lane == 0) {
                uint32_t la = smem_u32(&s_ex[p][0]);
                asm volatile("st.shared.v2.b64 [%0], {%1, %2};" :: "r"(la), "l"(key), "l"(xy) : "memory");
                asm volatile("st.shared.b32 [%0], %1;" :: "r"(smem_u32(&s_exz[p])), "f"(bz) : "memory");
            }
        }
        asm volatile("barrier.cluster.arrive.aligned;" ::: "memory");
        asm volatile("barrier.cluster.wait.aligned;"   ::: "memory");
        ull kk = 0, kxy = 0; float kz = 0.0f;
        if (lane < CLU) {
            uint32_t la = smem_u32(&s_ex[p][0]), ra;
            asm volatile("mapa.shared::cluster.u32 %0, %1, %2;" : "=r"(ra) : "r"(la), "r"((uint32_t)lane));
            asm volatile("ld.shared::cluster.v2.b64 {%0, %1}, [%2];" : "=l"(kk), "=l"(kxy) : "r"(ra));
        } else if (lane < 2*CLU) {
            uint32_t la = smem_u32(&s_exz[p]), ra;
            asm volatile("mapa.shared::cluster.u32 %0, %1, %2;" : "=r"(ra) : "r"(la), "r"((uint32_t)(lane - CLU)));
            asm volatile("ld.shared::cluster.b32 %0, [%1];" : "=f"(kz) : "r"(ra));
        }
        kz = __shfl_down_sync(0xffffffffu, kz, CLU);
#pragma unroll
        for (int o = 4; o; o >>= 1) {
            ull  ok = __shfl_xor_sync(0xffffffffu, kk,  o);
            ull  oxy= __shfl_xor_sync(0xffffffffu, kxy, o);
            float oz= __shfl_xor_sync(0xffffffffu, kz,  o);
            if (ok > kk) { kk = ok; kxy = oxy; kz = oz; }
        }
        kk  = __shfl_sync(0xffffffffu, kk,  0);
        kxy = __shfl_sync(0xffffffffu, kxy, 0);
        kz  = __shfl_sync(0xffffffffu, kz,  0);
        if (rank == 0 && t == 0) {
            fidx[(size_t)b*2048 + j] = 16383 - (int)(kk & 0x3FFFu);
            float wx, wy; upkxy(kxy, wx, wy);
            float* o = nxyz + ((size_t)b*2048 + j)*3;
            o[0] = wx; o[1] = wy; o[2] = kz;
        }
        upkxy(kxy, cx, cy); cz = kz;
    }
}

// ============ FPS stages 2-4 device body ============
template<int BLK, int P>
__device__ __forceinline__ void fps_reg_dev(const float* __restrict__ xyz, int npoint,
                                            int* __restrict__ fidx, float* __restrict__ nxyz,
                                            int b, float* sm)
{
    const int N = BLK * P;
    float* sx = sm; float* sy = sm + N; float* sz = sm + 2*N;
    __shared__ float rv[32];
    __shared__ int   ri[32];
    __shared__ float s_cxyz[3];

    const int t = threadIdx.x;
    const float* base = xyz + (size_t)b * N * 3;
    float px[P], py[P], pz[P], dst[P];
#pragma unroll
    for (int k = 0; k < P; k++) {
        int i = t + k*BLK;
        px[k] = base[i*3+0]; py[k] = base[i*3+1]; pz[k] = base[i*3+2];
        sx[i] = px[k]; sy[i] = py[k]; sz[i] = pz[k];
        dst[k] = 1e10f;
    }
    if (t == 0) {
        s_cxyz[0] = px[0]; s_cxyz[1] = py[0]; s_cxyz[2] = pz[0];
        fidx[(size_t)b*npoint] = 0;
        float* o = nxyz + (size_t)b*npoint*3;
        o[0] = px[0]; o[1] = py[0]; o[2] = pz[0];
    }
    __syncthreads();

    for (int j = 1; j < npoint; j++) {
        const float cx = s_cxyz[0], cy = s_cxyz[1], cz = s_cxyz[2];
        float best = -1.0f; int bi = 0x7fffffff;
#pragma unroll
        for (int k = 0; k < P; k++) {
            float dx = px[k]-cx, dy = py[k]-cy, dz = pz[k]-cz;
            float nd = fminf(dst[k], dx*dx + dy*dy + dz*dz);
            dst[k] = nd;
            if (nd > best) { best = nd; bi = t + k*BLK; }
        }
#pragma unroll
        for (int off = 16; off; off >>= 1) {
            float ov = __shfl_down_sync(0xffffffffu, best, off);
            int   oi = __shfl_down_sync(0xffffffffu, bi,   off);
            if (ov > best || (ov == best && oi < bi)) { best = ov; bi = oi; }
        }
        int w = t >> 5;
        if ((t & 31) == 0) { rv[w] = best; ri[w] = bi; }
        __syncthreads();
        if (t < 32) {
            const int nw = BLK / 32;
            float v  = (t < nw) ? rv[t] : -1.0f;
            int   i2 = (t < nw) ? ri[t] : 0x7fffffff;
#pragma unroll
            for (int off = 16; off; off >>= 1) {
                float ov = __shfl_down_sync(0xffffffffu, v,  off);
                int   oi = __shfl_down_sync(0xffffffffu, i2, off);
                if (ov > v || (ov == v && oi < i2)) { v = ov; i2 = oi; }
            }
            if (t == 0) {
                fidx[(size_t)b*npoint + j] = i2;
                float wx = sx[i2], wy = sy[i2], wz = sz[i2];
                s_cxyz[0] = wx; s_cxyz[1] = wy; s_cxyz[2] = wz;
                float* o = nxyz + ((size_t)b*npoint + j)*3;
                o[0] = wx; o[1] = wy; o[2] = wz;
            }
        }
        __syncthreads();
    }
}

__global__ void pack4_kernel(const float* __restrict__ xyz, float4* __restrict__ pk, int total)
{
    int i = blockIdx.x*blockDim.x + threadIdx.x;
    if (i >= total) return;
    float x = xyz[i*3+0], y = xyz[i*3+1], z = xyz[i*3+2];
    pk[i] = make_float4(x, y, z, (x*x + y*y) + z*z);
}

// ============ ball query device body (SoA, warp-per-center) ============
__device__ __forceinline__ void bq_dev(const float* __restrict__ xyz, const float* __restrict__ nxyz,
                                       int* __restrict__ nidx, int S, int N, int nsample,
                                       float r2, int gw)
{
    int lane = threadIdx.x & 31;
    int b = gw / S;
    const float* xb = xyz + (size_t)b * N * 3;
    float nx = nxyz[gw*3+0], ny = nxyz[gw*3+1], nz = nxyz[gw*3+2];
    float sn = (nx*nx + ny*ny) + nz*nz;
    int* out = nidx + (size_t)gw * nsample;

    int cnt = 0, first = -1;
    for (int base = 0; base < N; base += 32) {
        int j = base + lane;
        float x = xb[j*3+0], y = xb[j*3+1], z = xb[j*3+2];
        float sxx = (x*x + y*y) + z*z;
        float dot = (nx*x + ny*y) + nz*z;
        bool in = ((sn + sxx) - 2.0f*dot) < r2;
        unsigned m = __ballot_sync(0xffffffffu, in);
        if (in) {
            int pos = cnt + __popc(m & ((1u << lane) - 1u));
            if (pos < nsample) out[pos] = j;
        }
        if (first < 0 && m) first = base + __ffs(m) - 1;
        cnt += __popc(m);
        if (cnt >= nsample) break;
    }
    for (int p = cnt + lane; p < nsample; p += 32) out[p] = first;
}

// ============ stage-1 ball query body: SMEM-tiled cloud ============
#define BQ_CH 2048
__device__ __forceinline__ void bq1_dev(const float4* __restrict__ pk, const float* __restrict__ nxyz,
                                        int* __restrict__ nidx, int blk, float4* sp)
{
    const int t = threadIdx.x, w = t >> 5, lane = t & 31;
    const int gw = blk * 8 + w;
    const int b = gw >> 11;
    const float4* xb = pk + (size_t)b * 16384;
    const float nx = nxyz[gw*3+0], ny = nxyz[gw*3+1], nz = nxyz[gw*3+2];
    const float sn = (nx*nx + ny*ny) + nz*nz;
    int* out = nidx + (size_t)gw * 64;

    int cnt = 0, first = -1;
    bool done = false;
    for (int base = 0; base < 16384; base += BQ_CH) {
        __syncthreads();
#pragma unroll
        for (int q = 0; q < BQ_CH/256; q++)
            sp[t + q*256] = xb[base + t + q*256];
        __syncthreads();
        if (done) continue;
        for (int inner = 0; inner < BQ_CH; inner += 32) {
            float4 p = sp[inner + lane];
            float dot = (nx*p.x + ny*p.y) + nz*p.z;
            bool in = ((sn + p.w) - 2.0f*dot) < 0.04f;
            unsigned m = __ballot_sync(0xffffffffu, in);
            if (in) {
                int pos = cnt + __popc(m & ((1u << lane) - 1u));
                if (pos < 64) out[pos] = base + inner + lane;
            }
            if (first < 0 && m) first = base + inner + __ffs(m) - 1;
            cnt += __popc(m);
            if (cnt >= 64) { done = true; break; }
        }
    }
    for (int p = cnt + lane; p < 64; p += 32) out[p] = first;
}

// ============ sa1 device body (proven) ============
#define SA1_SMEM 12928
__device__ __forceinline__ void sa1_dev(const float* __restrict__ xyz, const float* __restrict__ nxyz,
                const int* __restrict__ nidx,
                const float* __restrict__ w0, const float* __restrict__ b0,
                const float* __restrict__ w1, const float* __restrict__ b1,
                const float* __restrict__ w2, const float* __restrict__ b2,
                float* __restrict__ feats, float radius, int ctr, float* sm)
{
    float* sW0 = sm;
    float* sB0 = sm + 192;
    float* sW1 = sm + 256;
    float* sB1 = sm + 4352;
    float* sB2 = sm + 4416;
    float* sR  = sm + 4544;
    float* sH0 = sm + 4736;
    float* sH1 = sm + 8832;

    const int t = threadIdx.x;
    const int b = ctr >> 11;

    for (int i = t; i < 192;  i += 128) sW0[i] = w0[i];
    if (t < 64) { sB0[t] = b0[t]; sB1[t] = b1[t]; }
    for (int i = t; i < 4096; i += 128) sW1[i] = w1[i];
    sB2[t] = b2[t];
    if (t < 64) {
        int id = nidx[(size_t)ctr*64 + t];
        const float* p = xyz + ((size_t)(b << 14) + id)*3;
        sR[t*3+0] = (p[0] - nxyz[ctr*3+0]) / radius;
        sR[t*3+1] = (p[1] - nxyz[ctr*3+1]) / radius;
        sR[t*3+2] = (p[2] - nxyz[ctr*3+2]) / radius;
    }
    __syncthreads();

    {
        int n = t & 63, half = t >> 6;
        float rx = sR[n*3+0], ry = sR[n*3+1], rz = sR[n*3+2];
#pragma unroll 8
        for (int cc = 0; cc < 32; cc++) {
            int c = half*32 + cc;
            float v = sB0[c] + rx*sW0[c] + ry*sW0[64+c] + rz*sW0[128+c];
            sH0[c*64 + n] = fmaxf(v, 0.0f);
        }
    }
    __syncthreads();

    const int ng = t & 15, cg = t >> 4;
    float acc[32];

#pragma unroll
    for (int i = 0; i < 4; i++)
#pragma unroll
        for (int jj = 0; jj < 8; jj++) acc[i*8+jj] = sB1[8*cg + jj];
#pragma unroll 8
    for (int k = 0; k < 64; k++) {
        float4 a = *(const float4*)&sH0[k*64 + 4*ng];
        float4 u = *(const float4*)&sW1[k*64 + 8*cg];
        float4 v = *(const float4*)&sW1[k*64 + 8*cg + 4];
        float av[4] = {a.x, a.y, a.z, a.w};
        float bv[8] = {u.x, u.y, u.z, u.w, v.x, v.y, v.z, v.w};
#pragma unroll
        for (int i = 0; i < 4; i++)
#pragma unroll
            for (int jj = 0; jj < 8; jj++) acc[i*8+jj] += av[i]*bv[jj];
    }
#pragma unroll
    for (int jj = 0; jj < 8; jj++) {
        float4 o;
        o.x = fmaxf(acc[0*8+jj], 0.0f);
        o.y = fmaxf(acc[1*8+jj], 0.0f);
        o.z = fmaxf(acc[2*8+jj], 0.0f);
        o.w = fmaxf(acc[3*8+jj], 0.0f);
        *(float4*)&sH1[(8*cg+jj)*64 + 4*ng] = o;
    }
    __syncthreads();

#pragma unroll 1
    for (int pass = 0; pass < 2; pass++) {
        int c0 = pass*64 + 8*cg;
#pragma unroll
        for (int i = 0; i < 4; i++)
#pragma unroll
            for (int jj = 0; jj < 8; jj++) acc[i*8+jj] = sB2[c0 + jj];
#pragma unroll 4
        for (int k = 0; k < 64; k++) {
            float4 a = *(const float4*)&sH1[k*64 + 4*ng];
            float4 u = *(const float4*)&w2[k*128 + c0];
            float4 v = *(const float4*)&w2[k*128 + c0 + 4];
            float av[4] = {a.x, a.y, a.z, a.w};
            float bv[8] = {u.x, u.y, u.z, u.w, v.x, v.y, v.z, v.w};
#pragma unroll
            for (int i = 0; i < 4; i++)
#pragma unroll
                for (int jj = 0; jj < 8; jj++) acc[i*8+jj] += av[i]*bv[jj];
        }
#pragma unroll
        for (int jj = 0; jj < 8; jj++) {
            float m = fmaxf(fmaxf(fmaxf(acc[0*8+jj], 0.0f), fmaxf(acc[1*8+jj], 0.0f)),
                            fmaxf(fmaxf(acc[2*8+jj], 0.0f), fmaxf(acc[3*8+jj], 0.0f)));
#pragma unroll
            for (int off = 8; off; off >>= 1)
                m = fmaxf(m, __shfl_xor_sync(0xffffffffu, m, off));
            if (ng == 0) feats[(size_t)ctr*128 + c0 + jj] = m;
        }
    }
}

// ============ GEMM device bodies: ping-pong SMEM double-buffer (R15-proven) ============
__device__ __forceinline__ void gemm128_dev(const float* __restrict__ A, const float* __restrict__ W,
             const float* __restrict__ bias, float* __restrict__ Y,
             int M, int N, int K, int bxv, int byv)
{
    __shared__ __align__(16) float As[2][8][128];
    __shared__ __align__(16) float Bs[2][8][128];
    const int bm = byv * 128;
    const int bn = bxv * 128;
    const int t  = threadIdx.x;
    const int ty = t >> 4, tx = t & 15;
    float acc[8][8];
#pragma unroll
    for (int i = 0; i < 8; i++)
#pragma unroll
        for (int j = 0; j < 8; j++) acc[i][j] = 0.0f;

    const int abr = t >> 5;
    const int abc = (t & 31) * 4;
    const int ar0 = (t*4) >> 3;
    const int ac0 = (t*4) & 7;

    float ra[4]; float4 rb;
#pragma unroll
    for (int q = 0; q < 4; q++) {
        int kk = ac0 + q;
        ra[q] = (kk < K) ? A[(size_t)(bm + ar0)*K + kk] : 0.0f;
    }
    rb = (abr < K) ? *(const float4*)&W[(size_t)abr*N + bn + abc]
                   : make_float4(0.f,0.f,0.f,0.f);
#pragma unroll
    for (int q = 0; q < 4; q++) As[0][ac0 + q][ar0] = ra[q];
    *(float4*)&Bs[0][abr][abc] = rb;
    __syncthreads();

    for (int k0 = 0; k0 < K; k0 += 8) {
        const int cur = (k0 >> 3) & 1;
        if (k0 + 8 < K) {
#pragma unroll
            for (int q = 0; q < 4; q++) {
                int kk = k0 + 8 + ac0 + q;
                ra[q] = (kk < K) ? A[(size_t)(bm + ar0)*K + kk] : 0.0f;
            }
            int kk = k0 + 8 + abr;
            rb = (kk < K) ? *(const float4*)&W[(size_t)kk*N + bn + abc]
                          : make_float4(0.f,0.f,0.f,0.f);
        }
#pragma unroll
        for (int kk = 0; kk < 8; kk++) {
            float4 a0 = *(const float4*)&As[cur][kk][ty*8];
            float4 a1 = *(const float4*)&As[cur][kk][ty*8 + 4];
            float4 b0 = *(const float4*)&Bs[cur][kk][tx*8];
            float4 b1 = *(const float4*)&Bs[cur][kk][tx*8 + 4];
            float av[8] = {a0.x, a0.y, a0.z, a0.w, a1.x, a1.y, a1.z, a1.w};
            float bv[8] = {b0.x, b0.y, b0.z, b0.w, b1.x, b1.y, b1.z, b1.w};
#pragma unroll
            for (int i = 0; i < 8; i++)
#pragma unroll
                for (int j = 0; j < 8; j++) acc[i][j] += av[i]*bv[j];
        }
        if (k0 + 8 < K) {
#pragma unroll
            for (int q = 0; q < 4; q++) As[cur^1][ac0 + q][ar0] = ra[q];
            *(float4*)&Bs[cur^1][abr][abc] = rb;
            __syncthreads();
        }
    }
    float4 bb0 = *(const float4*)&bias[bn + tx*8];
    float4 bb1 = *(const float4*)&bias[bn + tx*8 + 4];
    float bv[8] = {bb0.x, bb0.y, bb0.z, bb0.w, bb1.x, bb1.y, bb1.z, bb1.w};
#pragma unroll
    for (int i = 0; i < 8; i++) {
        size_t row = (size_t)(bm + ty*8 + i);
        float4 o0, o1;
        o0.x = fmaxf(acc[i][0]+bv[0], 0.f); o0.y = fmaxf(acc[i][1]+bv[1], 0.f);
        o0.z = fmaxf(acc[i][2]+bv[2], 0.f); o0.w = fmaxf(acc[i][3]+bv[3], 0.f);
        o1.x = fmaxf(acc[i][4]+bv[4], 0.f); o1.y = fmaxf(acc[i][5]+bv[5], 0.f);
        o1.z = fmaxf(acc[i][6]+bv[6], 0.f); o1.w = fmaxf(acc[i][7]+bv[7], 0.f);
        *(float4*)&Y[row*N + bn + tx*8]     = o0;
        *(float4*)&Y[row*N + bn + tx*8 + 4] = o1;
    }
}

__device__ __forceinline__ void gemm128g_dev(const float* __restrict__ xyz, const float* __restrict__ nxyz,
              const int* __restrict__ nidx, const float* __restrict__ feats,
              const float* __restrict__ W, const float* __restrict__ bias,
              float* __restrict__ Y, int M, int N, int K,
              int ns, int npts, int C, float radius, int rows_pb, int bxv, int byv)
{
    __shared__ __align__(16) float Asg[2][8][128];
    __shared__ __align__(16) float Bsg[2][8][128];
    const int bm = byv * 128;
    const int bn = bxv * 128;
    const int t  = threadIdx.x;
    const int ty = t >> 4, tx = t & 15;
    float acc[8][8];
#pragma unroll
    for (int i = 0; i < 8; i++)
#pragma unroll
        for (int j = 0; j < 8; j++) acc[i][j] = 0.0f;

    const int ar  = (t*4) >> 3;
    const int ac0 = (t*4) & 7;
    const int row = bm + ar;
    const int ci  = row / ns;
    const int b   = row / rows_pb;
    const int id  = nidx[row];
    const float* pt = xyz + ((size_t)b*npts + id)*3;
    const float* fr = feats + ((size_t)b*npts + id)*C;
    float rel[3];
#pragma unroll
    for (int cc = 0; cc < 3; cc++) rel[cc] = (pt[cc] - nxyz[ci*3+cc]) / radius;

    const int abr = t >> 5;
    const int abc = (t & 31) * 4;

    float ra[4]; float4 rb;
#pragma unroll
    for (int q = 0; q < 4; q++) {
        int kk = ac0 + q;
        ra[q] = (kk < 3) ? rel[kk] : ((kk < K) ? fr[kk-3] : 0.0f);
    }
    rb = (abr < K) ? *(const float4*)&W[(size_t)abr*N + bn + abc]
                   : make_float4(0.f,0.f,0.f,0.f);
#pragma unroll
    for (int q = 0; q < 4; q++) Asg[0][ac0 + q][ar] = ra[q];
    *(float4*)&Bsg[0][abr][abc] = rb;
    __syncthreads();

    for (int k0 = 0; k0 < K; k0 += 8) {
        const int cur = (k0 >> 3) & 1;
        if (k0 + 8 < K) {
#pragma unroll
            for (int q = 0; q < 4; q++) {
                int kk = k0 + 8 + ac0 + q;
                ra[q] = (kk < 3) ? rel[kk] : ((kk < K) ? fr[kk-3] : 0.0f);
            }
            int kk = k0 + 8 + abr;
            rb = (kk < K) ? *(const float4*)&W[(size_t)kk*N + bn + abc]
                          : make_float4(0.f,0.f,0.f,0.f);
        }
#pragma unroll
        for (int kk = 0; kk < 8; kk++) {
            float4 a0 = *(const float4*)&Asg[cur][kk][ty*8];
            float4 a1 = *(const float4*)&Asg[cur][kk][ty*8 + 4];
            float4 b0 = *(const float4*)&Bsg[cur][kk][tx*8];
            float4 b1 = *(const float4*)&Bsg[cur][kk][tx*8 + 4];
            float av[8] = {a0.x, a0.y, a0.z, a0.w, a1.x, a1.y, a1.z, a1.w};
            float bv[8] = {b0.x, b0.y, b0.z, b0.w, b1.x, b1.y, b1.z, b1.w};
#pragma unroll
            for (int i = 0; i < 8; i++)
#pragma unroll
                for (int j = 0; j < 8; j++) acc[i][j] += av[i]*bv[j];
        }
        if (k0 + 8 < K) {
#pragma unroll
            for (int q = 0; q < 4; q++) Asg[cur^1][ac0 + q][ar] = ra[q];
            *(float4*)&Bsg[cur^1][abr][abc] = rb;
            __syncthreads();
        }
    }
    float4 bb0 = *(const float4*)&bias[bn + tx*8];
    float4 bb1 = *(const float4*)&bias[bn + tx*8 + 4];
    float bv[8] = {bb0.x, bb0.y, bb0.z, bb0.w, bb1.x, bb1.y, bb1.z, bb1.w};
#pragma unroll
    for (int i = 0; i < 8; i++) {
        size_t orow = (size_t)(bm + ty*8 + i);
        float4 o0, o1;
        o0.x = fmaxf(acc[i][0]+bv[0], 0.f); o0.y = fmaxf(acc[i][1]+bv[1], 0.f);
        o0.z = fmaxf(acc[i][2]+bv[2], 0.f); o0.w = fmaxf(acc[i][3]+bv[3], 0.f);
        o1.x = fmaxf(acc[i][4]+bv[4], 0.f); o1.y = fmaxf(acc[i][5]+bv[5], 0.f);
        o1.z = fmaxf(acc[i][6]+bv[6], 0.f); o1.w = fmaxf(acc[i][7]+bv[7], 0.f);
        *(float4*)&Y[orow*N + bn + tx*8]     = o0;
        *(float4*)&Y[orow*N + bn + tx*8 + 4] = o1;
    }
}

__global__ __launch_bounds__(256)
void gemm128(const float* A, const float* W, const float* bias, float* Y, int M, int N, int K)
{ gemm128_dev(A, W, bias, Y, M, N, K, blockIdx.x, blockIdx.y); }

__global__ __launch_bounds__(256)
void gemm128g(const float* xyz, const float* nxyz, const int* nidx, const float* feats,
              const float* W, const float* bias, float* Y, int M, int N, int K,
              int ns, int npts, int C, float radius, int rows_pb)
{ gemm128g_dev(xyz, nxyz, nidx, feats, W, bias, Y, M, N, K, ns, npts, C, radius, rows_pb, blockIdx.x, blockIdx.y); }

// ============ GEMM + bias + relu + fused maxpool (ping-pong) ============
template<int NS>
__global__ __launch_bounds__(256)
void gemm128_mp(const float* __restrict__ A, const float* __restrict__ W,
                const float* __restrict__ bias, float* __restrict__ out,
                int M, int N, int K)
{
    __shared__ __align__(16) float As[2][8][128];
    __shared__ __align__(16) float Bs[2][8][128];
    __shared__ float red[16][136];
    const int bm = blockIdx.y * 128;
    const int bn = blockIdx.x * 128;
    const int t  = threadIdx.x;
    const int ty = t >> 4, tx = t & 15;
    float acc[8][8];
#pragma unroll
    for (int i = 0; i < 8; i++)
#pragma unroll
        for (int j = 0; j < 8; j++) acc[i][j] = 0.0f;

    const int abr = t >> 5;
    const int abc = (t & 31) * 4;
    const int ar0 = (t*4) >> 3;
    const int ac0 = (t*4) & 7;

    float ra[4]; float4 rb;
#pragma unroll
    for (int q = 0; q < 4; q++) {
        int kk = ac0 + q;
        ra[q] = (kk < K) ? A[(size_t)(bm + ar0)*K + kk] : 0.0f;
    }
    rb = (abr < K) ? *(const float4*)&W[(size_t)abr*N + bn + abc]
                   : make_float4(0.f,0.f,0.f,0.f);
#pragma unroll
    for (int q = 0; q < 4; q++) As[0][ac0 + q][ar0] = ra[q];
    *(float4*)&Bs[0][abr][abc] = rb;
    __syncthreads();

    for (int k0 = 0; k0 < K; k0 += 8) {
        const int cur = (k0 >> 3) & 1;
        if (k0 + 8 < K) {
#pragma unroll
            for (int q = 0; q < 4; q++) {
                int kk = k0 + 8 + ac0 + q;
                ra[q] = (kk < K) ? A[(size_t)(bm + ar0)*K + kk] : 0.0f;
            }
            int kk = k0 + 8 + abr;
            rb = (kk < K) ? *(const float4*)&W[(size_t)kk*N + bn + abc]
                          : make_float4(0.f,0.f,0.f,0.f);
        }
#pragma unroll
        for (int kk = 0; kk < 8; kk++) {
            float4 a0 = *(const float4*)&As[cur][kk][ty*8];
            float4 a1 = *(const float4*)&As[cur][kk][ty*8 + 4];
            float4 b0 = *(const float4*)&Bs[cur][kk][tx*8];
            float4 b1 = *(const float4*)&Bs[cur][kk][tx*8 + 4];
            float av[8] = {a0.x, a0.y, a0.z, a0.w, a1.x, a1.y, a1.z, a1.w};
            float bv[8] = {b0.x, b0.y, b0.z, b0.w, b1.x, b1.y, b1.z, b1.w};
#pragma unroll
            for (int i = 0; i < 8; i++)
#pragma unroll
                for (int j = 0; j < 8; j++) acc[i][j] += av[i]*bv[j];
        }
        if (k0 + 8 < K) {
#pragma unroll
            for (int q = 0; q < 4; q++) As[cur^1][ac0 + q][ar0] = ra[q];
            *(float4*)&Bs[cur^1][abr][abc] = rb;
            __syncthreads();
        }
    }
    float4 bb0 = *(const float4*)&bias[bn + tx*8];
    float4 bb1 = *(const float4*)&bias[bn + tx*8 + 4];
    float bv[8] = {bb0.x, bb0.y, bb0.z, bb0.w, bb1.x, bb1.y, bb1.z, bb1.w};
#pragma unroll
    for (int j = 0; j < 8; j++) {
        float m = fmaxf(acc[0][j] + bv[j], 0.0f);
#pragma unroll
        for (int i = 1; i < 8; i++) m = fmaxf(m, fmaxf(acc[i][j] + bv[j], 0.0f));
        red[ty][tx*8 + j] = m;
    }
    __syncthreads();
    const int g = NS / 8;
    if ((ty % g) == 0) {
        int center = (bm + ty*8) / NS;
#pragma unroll
        for (int j = 0; j < 8; j++) {
            float m = red[ty][tx*8 + j];
#pragma unroll
            for (int r = 1; r < g; r++) m = fmaxf(m, red[ty + r][tx*8 + j]);
            out[(size_t)center*N + bn + tx*8 + j] = m;
        }
    }
}

// ================== fat combo kernels — FPS FIRST (wave-1 placement) ==================
// L3 (256 thr, dyn 32KB): [0,4) fps2 | [4,1028) bq1
__global__ __launch_bounds__(256)
void combo_L3(const float4* pk4, const float* nx1, int* nidx1,
              int* fidx, float* nx2)
{
    extern __shared__ float smf[];
    int bid = blockIdx.x;
    if (bid < 4) {
        fps_reg_dev<256,8>(nx1, 1024, fidx, nx2, bid, smf);
    } else {
        bq1_dev(pk4, nx1, nidx1, bid - 4, (float4*)smf);
    }
}

// L4 (128 thr, dyn 51712B): [0,4) fps3 | [4,1028) bq2 (4 warps/blk) | [1028,9220) sa1
__global__ __launch_bounds__(128)
void combo_L4(const float* pc, const float* nx1, const int* nidx1,
              const float* w0, const float* b0, const float* w1, const float* b1,
              const float* w2, const float* b2, float* f1,
              const float* nx2, int* nidx2, int* fidx, float* nx3)
{
    extern __shared__ float smf[];
    int bid = blockIdx.x;
    if (bid < 4) {
        fps_reg_dev<128,8>(nx2, 512, fidx, nx3, bid, smf);
    } else if (bid < 1028) {
        int gw = (bid - 4)*4 + (threadIdx.x >> 5);
        bq_dev(nx1, nx2, nidx2, 1024, 2048, 32, 0.16f, gw);
    } else {
        sa1_dev(pc, nx1, nidx1, w0,b0,w1,b1,w2,b2, f1, 0.2f, bid - 1028, smf);
    }
}

// L5 (256 thr): [0,4) fps4 | [4,260) bq3 (8 warps/blk) | [260,1284) gemm_g2
__global__ __launch_bounds__(256)
void combo_L5(const float* nx1, const float* nx2, const int* nidx2, const float* f1,
              const float* w20, const float* b20, float* YA,
              const float* nx3, int* nidx3, int* fidx, float* nx4)
{
    extern __shared__ float smf[];
    int bid = blockIdx.x;
    if (bid < 4) {
        fps_reg_dev<256,2>(nx3, 256, fidx, nx4, bid, smf);
    } else if (bid < 260) {
        int gw = (bid - 4)*8 + (threadIdx.x >> 5);
        bq_dev(nx2, nx3, nidx3, 512, 1024, 16, 0.36f, gw);
    } else {
        gemm128g_dev(nx1, nx2, nidx2, f1, w20, b20, YA, 131072, 128, 131, 32, 2048, 128, 0.4f, 32768, 0, bid - 260);
    }
}

// L6 (256 thr): [0,128) bq4 (8 warps/blk) | [128,1152) gemm mid-2
__global__ __launch_bounds__(256)
void combo_L6(const float* YA, const float* w21, const float* b21, float* YB,
              const float* nx3, const float* nx4, int* nidx4)
{
    int bid = blockIdx.x;
    if (bid < 128) {
        int gw = bid*8 + (threadIdx.x >> 5);
        bq_dev(nx3, nx4, nidx4, 256, 512, 8, 1.44f, gw);
    } else {
        gemm128_dev(YA, w21, b21, YB, 131072, 128, 128, 0, bid - 128);
    }
}

static inline int cdiv(int a, int b) { return (a + b - 1) / b; }

extern "C" void kernel_launch(void* const* d_in, const int* in_sizes, int n_in,
                              void* d_out, int out_size)
{
    (void)in_sizes; (void)n_in; (void)out_size;
    const float* pc  = (const float*)d_in[0];
    const float* w10 = (const float*)d_in[1],  *b10 = (const float*)d_in[2];
    const float* w11 = (const float*)d_in[3],  *b11 = (const float*)d_in[4];
    const float* w12 = (const float*)d_in[5],  *b12 = (const float*)d_in[6];
    const float* w20 = (const float*)d_in[7],  *b20 = (const float*)d_in[8];
    const float* w21 = (const float*)d_in[9],  *b21 = (const float*)d_in[10];
    const float* w22 = (const float*)d_in[11], *b22 = (const float*)d_in[12];
    const float* w30 = (const float*)d_in[13], *b30 = (const float*)d_in[14];
    const float* w31 = (const float*)d_in[15], *b31 = (const float*)d_in[16];
    const float* w32 = (const float*)d_in[17], *b32 = (const float*)d_in[18];
    const float* w40 = (const float*)d_in[19], *b40 = (const float*)d_in[20];
    const float* w41 = (const float*)d_in[21], *b41 = (const float*)d_in[22];
    const float* w42 = (const float*)d_in[23], *b42 = (const float*)d_in[24];

    float *nx1, *nx2, *nx3, *f1, *f2, *f3, *YA, *YB;
    float4 *pk4;
    int *fidx, *nidx;
    cudaGetSymbolAddress((void**)&nx1,  g_nx1);
    cudaGetSymbolAddress((void**)&nx2,  g_nx2);
    cudaGetSymbolAddress((void**)&nx3,  g_nx3);
    cudaGetSymbolAddress((void**)&f1,   g_f1);
    cudaGetSymbolAddress((void**)&f2,   g_f2);
    cudaGetSymbolAddress((void**)&f3,   g_f3);
    cudaGetSymbolAddress((void**)&YA,   g_YA);
    cudaGetSymbolAddress((void**)&YB,   g_YB);
    cudaGetSymbolAddress((void**)&fidx, g_fidx);
    cudaGetSymbolAddress((void**)&nidx, g_nidx);
    cudaGetSymbolAddress((void**)&pk4,  g_pk4);
    int* nidx1 = nidx;
    int* nidx2 = nidx + 524288;
    int* nidx3 = nidx + 655360;
    int* nidx4 = nidx + 688128;

    cudaFuncSetAttribute((const void*)combo_L4,
                         cudaFuncAttributeMaxDynamicSharedMemorySize, SA1_SMEM*4);

    float* out = (float*)d_out;
    float* nx4 = out;          // [4,256,3]
    float* f4  = out + 3072;   // [4,256,512]

    pack4_kernel<<<cdiv(NB*16384,256),256>>>(pc, pk4, NB*16384);
    fps1_cluster<<<NB*CLU, 256>>>(pc, fidx, nx1);
    combo_L3<<<1028, 256, 32768>>>(pk4, nx1, nidx1, fidx, nx2);
    combo_L4<<<9220, 128, SA1_SMEM*4>>>(pc, nx1, nidx1, w10,b10,w11,b11,w12,b12, f1,
                                        nx2, nidx2, fidx, nx3);
    combo_L5<<<1284, 256, 6144>>>(nx1, nx2, nidx2, f1, w20, b20, YA, nx3, nidx3, fidx, nx4);
    combo_L6<<<1152, 256>>>(YA, w21, b21, YB, nx3, nx4, nidx4);
    gemm128_mp<32><<<dim3(2, 1024), 256>>>(YB, w22, b22, f2, 131072, 256, 128);

    // Stage 3 MLP
    gemm128g<<<dim3(2, 256), 256>>>(nx2, nx3, nidx3, f2, w30, b30, YA, 32768, 256, 259, 16, 1024, 256, 0.6f, 8192);
    gemm128<<<dim3(2, 256), 256>>>(YA, w31, b31, YB, 32768, 256, 256);
    gemm128_mp<16><<<dim3(4, 256), 256>>>(YB, w32, b32, f3, 32768, 512, 256);

    // Stage 4 MLP
    gemm128g<<<dim3(4, 64), 256>>>(nx3, nx4, nidx4, f3, w40, b40, YA, 8192, 512, 515, 8, 512, 512, 1.2f, 2048);
    gemm128<<<dim3(4, 64), 256>>>(YA, w41, b41, YB, 8192, 512, 512);
    gemm128_mp<8><<<dim3(4, 64), 256>>>(YB, w42, b42, f4, 8192, 512, 512);
}